// round 2
// baseline (speedup 1.0000x reference)
#include <cuda_runtime.h>
#include <cuda_bf16.h>
#include <cstdint>
#include <cstddef>

// ---------------------------------------------------------------------------
// TaggingFNNDecoder: 2-layer LSTM tag decoder. B=32, T=256, D=1024, H=512, K=128
//   k_pack  : repack weights into concatenated per-row layout (once per launch)
//   k_init  : transpose initial h/c states into [feat][batch]
//   k_initsm: raw initial tag logits from hiddens[:,0,:512]
//   k_pre   : SGEMM  pre0[t][row][b] = x @ W_ih0[:,:1024]^T + b_ih0 + b_hh0
//   loop t  : k_cell0 (softmax(prev logits) inline + LSTM0),
//             k_cell1 (LSTM1), k_out (logits)
//   k_final : masked softmax -> out [B,T,K]
// ---------------------------------------------------------------------------

#define B_  32
#define T_  256
#define D_  1024
#define H_  512
#define K_  128
#define R_  2048    // 4*H gate rows
#define KC0 640     // cell0 reduced k-dim: h1(512) + sm(128)
#define KC1 1024    // cell1 k-dim: h1(512) + h2(512)
#define S0  33      // padded batch stride in smem (bank-conflict-free)

// ------------------------- device scratch ----------------------------------
__device__ float d_pre0[(size_t)T_ * R_ * B_];   // 64 MB [t][row][b]
__device__ float d_W0[(size_t)R_ * KC0];         // [row][ W_hh0 | W_ih0[:,1024:] ]
__device__ float d_W1[(size_t)R_ * KC1];         // [row][ W_ih1 | W_hh1 ]
__device__ float d_bias1[R_];
__device__ float d_h1[2 * H_ * B_];              // double buffered [j][b]
__device__ float d_h2[2 * H_ * B_];
__device__ float d_c1[H_ * B_];
__device__ float d_c2[H_ * B_];
__device__ float d_logit0[K_ * B_];              // [k][b] initial tag logits
__device__ float d_logits[(size_t)T_ * K_ * B_]; // [t][k][b] raw logits

__device__ __forceinline__ float sigf(float x) {
    return 1.0f / (1.0f + __expf(-x));
}

// ----------------------------- weight repack --------------------------------
__global__ void k_pack(const float* __restrict__ Wih0, const float* __restrict__ Whh0,
                       const float* __restrict__ Wih1, const float* __restrict__ Whh1,
                       const float* __restrict__ bih1, const float* __restrict__ bhh1) {
    int row = blockIdx.x;          // 0..2047
    int tid = threadIdx.x;         // 256 threads
    // d_W0 row: [W_hh0 row (512) | W_ih0 row cols 1024..1151 (128)]
    const float4* s1 = (const float4*)(Whh0 + (size_t)row * H_);
    float4* dW0 = (float4*)(d_W0 + (size_t)row * KC0);
    for (int i = tid; i < H_ / 4; i += 256) dW0[i] = s1[i];
    const float4* s2 = (const float4*)(Wih0 + (size_t)row * (D_ + K_) + D_);
    for (int i = tid; i < K_ / 4; i += 256) dW0[H_ / 4 + i] = s2[i];
    // d_W1 row: [W_ih1 row (512) | W_hh1 row (512)]
    float4* dW1 = (float4*)(d_W1 + (size_t)row * KC1);
    const float4* s3 = (const float4*)(Wih1 + (size_t)row * H_);
    const float4* s4 = (const float4*)(Whh1 + (size_t)row * H_);
    for (int i = tid; i < H_ / 4; i += 256) { dW1[i] = s3[i]; dW1[H_ / 4 + i] = s4[i]; }
    if (tid == 0) d_bias1[row] = bih1[row] + bhh1[row];
}

// ----------------------------- state init -----------------------------------
__global__ void k_init(const float* __restrict__ h_t, const float* __restrict__ c_t) {
    int idx = blockIdx.x * blockDim.x + threadIdx.x;   // 0..16383 = j*32+b
    if (idx < H_ * B_) {
        int j = idx >> 5, b = idx & 31;
        d_h1[idx] = h_t[b * H_ + j];                   // layer0, buffer 0
        d_h2[idx] = h_t[B_ * H_ + b * H_ + j];         // layer1, buffer 0
        d_c1[idx] = c_t[b * H_ + j];
        d_c2[idx] = c_t[B_ * H_ + b * H_ + j];
    }
}

// ------------------- initial tag logits (raw, no softmax) -------------------
__global__ void k_initsm(const float* __restrict__ hid, const float* __restrict__ W_out,
                         const float* __restrict__ b_out) {
    int b = blockIdx.x;            // 32 blocks
    int k = threadIdx.x;           // 128 threads
    const float* x  = hid + (size_t)b * T_ * D_;       // hiddens[b][0][:]
    const float* wr = W_out + (size_t)k * H_;
    float a0 = 0.f, a1 = 0.f, a2 = 0.f, a3 = 0.f;
    for (int j = 0; j < H_; j += 4) {
        float4 w4 = *(const float4*)(wr + j);
        a0 += w4.x * x[j + 0];
        a1 += w4.y * x[j + 1];
        a2 += w4.z * x[j + 2];
        a3 += w4.w * x[j + 3];
    }
    d_logit0[k * B_ + b] = (a0 + a1) + (a2 + a3) + b_out[k];
}

// -------------- pre-projection SGEMM: C[m][n], m = b*256+t -------------------
// C = A(8192x1024) * W(2048x1152, first 1024 cols)^T ; scatter to d_pre0[t][n][b]
__global__ void __launch_bounds__(256) k_pre(const float* __restrict__ A,
                                             const float* __restrict__ W,
                                             const float* __restrict__ bih,
                                             const float* __restrict__ bhh) {
    __shared__ float As[8][132];
    __shared__ float Bs[8][132];
    int tid = threadIdx.x;
    int m0 = blockIdx.y * 128;
    int n0 = blockIdx.x * 128;
    int lr = tid >> 1;             // 0..127
    int lc = (tid & 1) * 4;        // 0 or 4
    int ty = tid >> 4;             // 0..15
    int tx = tid & 15;             // 0..15

    float acc[8][8];
#pragma unroll
    for (int i = 0; i < 8; i++)
#pragma unroll
        for (int j = 0; j < 8; j++) acc[i][j] = 0.f;

    for (int kt = 0; kt < D_; kt += 8) {
        float4 a = *(const float4*)&A[(size_t)(m0 + lr) * D_ + kt + lc];
        As[lc + 0][lr] = a.x; As[lc + 1][lr] = a.y;
        As[lc + 2][lr] = a.z; As[lc + 3][lr] = a.w;
        float4 b = *(const float4*)&W[(size_t)(n0 + lr) * (D_ + K_) + kt + lc];
        Bs[lc + 0][lr] = b.x; Bs[lc + 1][lr] = b.y;
        Bs[lc + 2][lr] = b.z; Bs[lc + 3][lr] = b.w;
        __syncthreads();
#pragma unroll
        for (int k = 0; k < 8; k++) {
            float ra[8], rb[8];
            *(float4*)&ra[0] = *(const float4*)&As[k][ty * 4];
            *(float4*)&ra[4] = *(const float4*)&As[k][64 + ty * 4];
            *(float4*)&rb[0] = *(const float4*)&Bs[k][tx * 4];
            *(float4*)&rb[4] = *(const float4*)&Bs[k][64 + tx * 4];
#pragma unroll
            for (int i = 0; i < 8; i++)
#pragma unroll
                for (int j = 0; j < 8; j++) acc[i][j] += ra[i] * rb[j];
        }
        __syncthreads();
    }

#pragma unroll
    for (int i = 0; i < 8; i++) {
        int m = m0 + ((i < 4) ? (ty * 4 + i) : (64 + ty * 4 + i - 4));
        int tt = m & 255;
        int bb = m >> 8;
#pragma unroll
        for (int j = 0; j < 8; j++) {
            int n = n0 + ((j < 4) ? (tx * 4 + j) : (64 + tx * 4 + j - 4));
            d_pre0[((size_t)tt * R_ + n) * B_ + bb] = acc[i][j] + bih[n] + bhh[n];
        }
    }
}

// ------------------------------ LSTM cell 0 ---------------------------------
// 256 blocks x 256 threads. Block owns 2 hidden units (8 gate rows).
// smem inp: rows 0..511 = h1_old, rows 512..639 = softmax(prev logits), stride 33.
__global__ void __launch_bounds__(256) k_cell0(int t) {
    extern __shared__ float smem[];
    float* inp  = smem;                       // KC0 * S0
    float* gact = smem + KC0 * S0;            // 8 * 32
    int tid = threadIdx.x, lane = tid & 31, w = tid >> 5;
    int old = t & 1;
    const float* __restrict__ h1old = d_h1 + old * (H_ * B_);

    // stage h1_old (transpose [j][b] -> stride-33)
    {
        const float4* src = (const float4*)h1old;
        for (int i = tid; i < (H_ * B_) / 4; i += 256) {
            float4 v = src[i];
            int j = i >> 3, c = (i & 7) * 4;
            float* d = inp + j * S0 + c;
            d[0] = v.x; d[1] = v.y; d[2] = v.z; d[3] = v.w;
        }
    }
    // stage raw previous logits into rows 512..639
    {
        const float* lg = (t == 0) ? d_logit0 : (d_logits + (size_t)(t - 1) * K_ * B_);
        const float4* src = (const float4*)lg;
        for (int i = tid; i < (K_ * B_) / 4; i += 256) {
            float4 v = src[i];
            int j = H_ + (i >> 3), c = (i & 7) * 4;
            float* d = inp + j * S0 + c;
            d[0] = v.x; d[1] = v.y; d[2] = v.z; d[3] = v.w;
        }
    }
    __syncthreads();

    // in-place softmax over k for 4 batches per warp
    {
        int b = w * 4;
#pragma unroll
        for (int bb = 0; bb < 4; bb++, b = w * 4 + bb) {
            float v[4];
#pragma unroll
            for (int i = 0; i < 4; i++) v[i] = inp[(H_ + lane + 32 * i) * S0 + b];
            float mx = fmaxf(fmaxf(v[0], v[1]), fmaxf(v[2], v[3]));
#pragma unroll
            for (int o = 16; o > 0; o >>= 1) mx = fmaxf(mx, __shfl_xor_sync(~0u, mx, o));
            float s = 0.f;
#pragma unroll
            for (int i = 0; i < 4; i++) { v[i] = __expf(v[i] - mx); s += v[i]; }
#pragma unroll
            for (int o = 16; o > 0; o >>= 1) s += __shfl_xor_sync(~0u, s, o);
            float inv = 1.0f / s;
#pragma unroll
            for (int i = 0; i < 4; i++) inp[(H_ + lane + 32 * i) * S0 + b] = v[i] * inv;
        }
    }
    __syncthreads();

    // dot: warp w -> (jl = w>>2, gate g = w&3), row = g*512 + j
    int jl = w >> 2, g = w & 3;
    int j = blockIdx.x * 2 + jl;
    int row = g * H_ + j;
    const float* __restrict__ wr = d_W0 + (size_t)row * KC0;
    float a0 = d_pre0[((size_t)t * R_ + row) * B_ + lane];
    float a1 = 0.f, a2 = 0.f, a3 = 0.f;
#pragma unroll 4
    for (int k = 0; k < KC0; k += 4) {
        float4 wv = *(const float4*)(wr + k);
        a0 += wv.x * inp[(k + 0) * S0 + lane];
        a1 += wv.y * inp[(k + 1) * S0 + lane];
        a2 += wv.z * inp[(k + 2) * S0 + lane];
        a3 += wv.w * inp[(k + 3) * S0 + lane];
    }
    gact[w * 32 + lane] = (a0 + a1) + (a2 + a3);
    __syncthreads();

    if (tid < 64) {
        int b = tid & 31, j2l = tid >> 5;
        int j2 = blockIdx.x * 2 + j2l;
        float iv = sigf(gact[(j2l * 4 + 0) * 32 + b]);
        float fv = sigf(gact[(j2l * 4 + 1) * 32 + b]);
        float gv = tanhf(gact[(j2l * 4 + 2) * 32 + b]);
        float ov = sigf(gact[(j2l * 4 + 3) * 32 + b]);
        float c = fv * d_c1[j2 * B_ + b] + iv * gv;
        d_c1[j2 * B_ + b] = c;
        d_h1[(old ^ 1) * (H_ * B_) + j2 * B_ + b] = ov * tanhf(c);
    }
}

// ------------------------------ LSTM cell 1 ---------------------------------
// 128 blocks x 512 threads. Block owns 4 hidden units (16 gate rows).
__global__ void __launch_bounds__(512) k_cell1(int t) {
    extern __shared__ float smem[];
    float* inp  = smem;                        // KC1 * S0
    float* gact = smem + KC1 * S0;             // 16 * 32
    int tid = threadIdx.x, lane = tid & 31, w = tid >> 5;   // 16 warps
    int old = t & 1;
    const float* __restrict__ h1new = d_h1 + (old ^ 1) * (H_ * B_);
    const float* __restrict__ h2old = d_h2 + old * (H_ * B_);

    {
        const float4* s1 = (const float4*)h1new;
        const float4* s2 = (const float4*)h2old;
        for (int i = tid; i < (H_ * B_) / 4; i += 512) {
            float4 v = s1[i];
            int j = i >> 3, c = (i & 7) * 4;
            float* d = inp + j * S0 + c;
            d[0] = v.x; d[1] = v.y; d[2] = v.z; d[3] = v.w;
            v = s2[i];
            d = inp + (H_ + j) * S0 + c;
            d[0] = v.x; d[1] = v.y; d[2] = v.z; d[3] = v.w;
        }
    }
    __syncthreads();

    int jl = w >> 2, g = w & 3;                // jl 0..3
    int j = blockIdx.x * 4 + jl;
    int row = g * H_ + j;
    const float* __restrict__ wr = d_W1 + (size_t)row * KC1;
    float a0 = d_bias1[row], a1 = 0.f, a2 = 0.f, a3 = 0.f;
#pragma unroll 4
    for (int k = 0; k < KC1; k += 4) {
        float4 wv = *(const float4*)(wr + k);
        a0 += wv.x * inp[(k + 0) * S0 + lane];
        a1 += wv.y * inp[(k + 1) * S0 + lane];
        a2 += wv.z * inp[(k + 2) * S0 + lane];
        a3 += wv.w * inp[(k + 3) * S0 + lane];
    }
    gact[w * 32 + lane] = (a0 + a1) + (a2 + a3);
    __syncthreads();

    if (tid < 128) {
        int b = tid & 31, j2l = tid >> 5;      // 0..3
        int j2 = blockIdx.x * 4 + j2l;
        float iv = sigf(gact[(j2l * 4 + 0) * 32 + b]);
        float fv = sigf(gact[(j2l * 4 + 1) * 32 + b]);
        float gv = tanhf(gact[(j2l * 4 + 2) * 32 + b]);
        float ov = sigf(gact[(j2l * 4 + 3) * 32 + b]);
        float c = fv * d_c2[j2 * B_ + b] + iv * gv;
        d_c2[j2 * B_ + b] = c;
        d_h2[(old ^ 1) * (H_ * B_) + j2 * B_ + b] = ov * tanhf(c);
    }
}

// ------------------------ output projection (raw logits) --------------------
// 16 blocks x 256 threads; warp w handles tag k = bid*8 + w, lane = batch.
__global__ void __launch_bounds__(256) k_out(int t, const float* __restrict__ W_out,
                                             const float* __restrict__ b_out) {
    extern __shared__ float smem[];            // H_ * S0
    int tid = threadIdx.x, lane = tid & 31, w = tid >> 5;
    const float* __restrict__ h2new = d_h2 + ((t & 1) ^ 1) * (H_ * B_);
    {
        const float4* src = (const float4*)h2new;
        for (int i = tid; i < (H_ * B_) / 4; i += 256) {
            float4 v = src[i];
            int j = i >> 3, c = (i & 7) * 4;
            float* d = smem + j * S0 + c;
            d[0] = v.x; d[1] = v.y; d[2] = v.z; d[3] = v.w;
        }
    }
    __syncthreads();

    int k = blockIdx.x * 8 + w;
    const float* __restrict__ wr = W_out + (size_t)k * H_;
    float a0 = b_out[k], a1 = 0.f, a2 = 0.f, a3 = 0.f;
#pragma unroll 4
    for (int j = 0; j < H_; j += 4) {
        float4 wv = *(const float4*)(wr + j);
        a0 += wv.x * smem[(j + 0) * S0 + lane];
        a1 += wv.y * smem[(j + 1) * S0 + lane];
        a2 += wv.z * smem[(j + 2) * S0 + lane];
        a3 += wv.w * smem[(j + 3) * S0 + lane];
    }
    d_logits[((size_t)t * K_ + k) * B_ + lane] = (a0 + a1) + (a2 + a3);
}

// --------------------------- final masked softmax ----------------------------
// 1024 blocks x 256 threads; warp per (b, t) pair.
__global__ void __launch_bounds__(256) k_final(const float* __restrict__ mask,
                                               float* __restrict__ out) {
    int tid = threadIdx.x, lane = tid & 31, w = tid >> 5;
    int gidx = blockIdx.x * 8 + w;             // 0..8191
    int b = gidx >> 8, t = gidx & 255;
    float pen = (1.0f - mask[b * T_ + t]) * -1e32f;
    float v[4];
#pragma unroll
    for (int i = 0; i < 4; i++)
        v[i] = d_logits[((size_t)t * K_ + lane + 32 * i) * B_ + b] + pen;
    float mx = fmaxf(fmaxf(v[0], v[1]), fmaxf(v[2], v[3]));
#pragma unroll
    for (int o = 16; o > 0; o >>= 1) mx = fmaxf(mx, __shfl_xor_sync(~0u, mx, o));
    float s = 0.f;
#pragma unroll
    for (int i = 0; i < 4; i++) { v[i] = __expf(v[i] - mx); s += v[i]; }
#pragma unroll
    for (int o = 16; o > 0; o >>= 1) s += __shfl_xor_sync(~0u, s, o);
    float inv = 1.0f / s;
#pragma unroll
    for (int i = 0; i < 4; i++)
        out[((size_t)b * T_ + t) * K_ + lane + 32 * i] = v[i] * inv;
}

// ----------------------------------------------------------------------------
extern "C" void kernel_launch(void* const* d_in, const int* in_sizes, int n_in,
                              void* d_out, int out_size) {
    const float* hiddens = (const float*)d_in[0];
    const float* h_t     = (const float*)d_in[1];
    const float* c_t     = (const float*)d_in[2];
    const float* mask    = (const float*)d_in[3];
    const float* W_out   = (const float*)d_in[4];
    const float* b_out   = (const float*)d_in[5];
    const float* W_ih0   = (const float*)d_in[6];
    const float* W_hh0   = (const float*)d_in[7];
    const float* b_ih0   = (const float*)d_in[8];
    const float* b_hh0   = (const float*)d_in[9];
    const float* W_ih1   = (const float*)d_in[10];
    const float* W_hh1   = (const float*)d_in[11];
    const float* b_ih1   = (const float*)d_in[12];
    const float* b_hh1   = (const float*)d_in[13];
    float* out = (float*)d_out;

    const int SMEM0 = (KC0 * S0 + 8 * 32) * 4;    // 85504
    const int SMEM1 = (KC1 * S0 + 16 * 32) * 4;   // 137216
    const int SMEMO = (H_ * S0) * 4;              // 67584
    cudaFuncSetAttribute(k_cell0, cudaFuncAttributeMaxDynamicSharedMemorySize, SMEM0);
    cudaFuncSetAttribute(k_cell1, cudaFuncAttributeMaxDynamicSharedMemorySize, SMEM1);
    cudaFuncSetAttribute(k_out,   cudaFuncAttributeMaxDynamicSharedMemorySize, SMEMO);

    k_pack<<<R_, 256>>>(W_ih0, W_hh0, W_ih1, W_hh1, b_ih1, b_hh1);
    k_init<<<64, 256>>>(h_t, c_t);
    k_initsm<<<B_, K_>>>(hiddens, W_out, b_out);
    k_pre<<<dim3(16, 64), 256>>>(hiddens, W_ih0, b_ih0, b_hh0);

    for (int t = 0; t < T_; t++) {
        k_cell0<<<256, 256, SMEM0>>>(t);
        k_cell1<<<128, 512, SMEM1>>>(t);
        k_out<<<16, 256, SMEMO>>>(t, W_out, b_out);
    }

    k_final<<<1024, 256>>>(mask, out);
}

// round 3
// speedup vs baseline: 2.6290x; 2.6290x over previous
#include <cuda_runtime.h>
#include <cuda_bf16.h>
#include <cstdint>
#include <cstddef>

// ---------------------------------------------------------------------------
// TaggingFNNDecoder: 2-layer LSTM tag decoder. B=32, T=256, D=1024, H=512, K=128
// Round 2: persistent-kernel recurrence.
//   k_pack  : repack weights (once per launch)
//   k_init  : transpose initial h/c states into [feat][batch]
//   k_initsm: raw initial tag logits from hiddens[:,0,:512]
//   k_pre   : SGEMM  pre0[t][row][b] = x @ W_ih0[:,:1024]^T + b_ih0 + b_hh0
//   k_loop  : persistent kernel, 128 CTAs, weights SMEM-resident, custom
//             grid barrier, full 256-step recurrence (cell0+cell1+out)
//   k_final : masked softmax -> out [B,T,K]
// ---------------------------------------------------------------------------

#define B_  32
#define T_  256
#define D_  1024
#define H_  512
#define K_  128
#define R_  2048    // 4*H gate rows
#define KC0 640     // cell0 reduced k-dim: h1(512) + sm(128)
#define KC1 1024    // cell1 k-dim: h1(512) + h2(512)
#define G_  128     // persistent grid size (<= 148 SMs, 1 CTA/SM)

// ------------------------- device scratch ----------------------------------
__device__ float d_pre0[(size_t)T_ * R_ * B_];   // 64 MB [t][row][b]
__device__ float d_W0[(size_t)R_ * KC0];         // [row][ W_hh0 | W_ih0[:,1024:] ]
__device__ float d_W1[(size_t)R_ * KC1];         // [row][ W_ih1 | W_hh1 ]
__device__ float d_bias1[R_];
__device__ float d_h1[2 * H_ * B_];              // double buffered [j][b]
__device__ float d_h2[2 * H_ * B_];
__device__ float d_c1[H_ * B_];
__device__ float d_c2[H_ * B_];
__device__ float d_logit0[K_ * B_];              // [k][b] initial tag logits
__device__ float d_logits[(size_t)T_ * K_ * B_]; // [t][k][b] raw logits

// barrier state
__device__ unsigned g_barcnt;
__device__ unsigned g_bargen;

__device__ __forceinline__ float sigf(float x) {
    return 1.0f / (1.0f + __expf(-x));
}

// packed fp32x2 helpers
__device__ __forceinline__ unsigned long long pk2(float x) {
    unsigned long long r; unsigned u = __float_as_uint(x);
    asm("mov.b64 %0, {%1, %1};" : "=l"(r) : "r"(u));
    return r;
}
__device__ __forceinline__ void fma2(unsigned long long& a,
                                     unsigned long long x, unsigned long long w) {
    asm("fma.rn.f32x2 %0, %1, %2, %0;" : "+l"(a) : "l"(x), "l"(w));
}
__device__ __forceinline__ void unpk2(float& lo, float& hi, unsigned long long v) {
    unsigned l, h;
    asm("mov.b64 {%0, %1}, %2;" : "=r"(l), "=r"(h) : "l"(v));
    lo = __uint_as_float(l); hi = __uint_as_float(h);
}

// grid barrier: atomic arrive, volatile-load spin, threadfence for visibility
// (threadfence at gpu scope also invalidates L1D per sm_103a behavior)
__device__ __forceinline__ void gbar(unsigned& gen) {
    __syncthreads();
    if (threadIdx.x == 0) {
        __threadfence();
        unsigned arrived = atomicAdd(&g_barcnt, 1);
        if (arrived == G_ - 1) {
            atomicExch(&g_barcnt, 0);
            __threadfence();
            atomicAdd(&g_bargen, 1);
        } else {
            while (*(volatile unsigned*)&g_bargen == gen) {}
        }
        gen++;
        __threadfence();
    }
    __syncthreads();
}

// ----------------------------- weight repack --------------------------------
__global__ void k_pack(const float* __restrict__ Wih0, const float* __restrict__ Whh0,
                       const float* __restrict__ Wih1, const float* __restrict__ Whh1,
                       const float* __restrict__ bih1, const float* __restrict__ bhh1) {
    int row = blockIdx.x;          // 0..2047
    int tid = threadIdx.x;         // 256 threads
    const float4* s1 = (const float4*)(Whh0 + (size_t)row * H_);
    float4* dW0 = (float4*)(d_W0 + (size_t)row * KC0);
    for (int i = tid; i < H_ / 4; i += 256) dW0[i] = s1[i];
    const float4* s2 = (const float4*)(Wih0 + (size_t)row * (D_ + K_) + D_);
    for (int i = tid; i < K_ / 4; i += 256) dW0[H_ / 4 + i] = s2[i];
    float4* dW1 = (float4*)(d_W1 + (size_t)row * KC1);
    const float4* s3 = (const float4*)(Wih1 + (size_t)row * H_);
    const float4* s4 = (const float4*)(Whh1 + (size_t)row * H_);
    for (int i = tid; i < H_ / 4; i += 256) { dW1[i] = s3[i]; dW1[H_ / 4 + i] = s4[i]; }
    if (tid == 0) d_bias1[row] = bih1[row] + bhh1[row];
}

// ----------------------------- state init -----------------------------------
__global__ void k_init(const float* __restrict__ h_t, const float* __restrict__ c_t) {
    int idx = blockIdx.x * blockDim.x + threadIdx.x;   // 0..16383 = j*32+b
    if (idx < H_ * B_) {
        int j = idx >> 5, b = idx & 31;
        d_h1[idx] = h_t[b * H_ + j];                   // layer0, buffer 0
        d_h2[idx] = h_t[B_ * H_ + b * H_ + j];         // layer1, buffer 0
        d_c1[idx] = c_t[b * H_ + j];
        d_c2[idx] = c_t[B_ * H_ + b * H_ + j];
    }
}

// ------------------- initial tag logits (raw, no softmax) -------------------
__global__ void k_initsm(const float* __restrict__ hid, const float* __restrict__ W_out,
                         const float* __restrict__ b_out) {
    int b = blockIdx.x;            // 32 blocks
    int k = threadIdx.x;           // 128 threads
    const float* x  = hid + (size_t)b * T_ * D_;       // hiddens[b][0][:]
    const float* wr = W_out + (size_t)k * H_;
    float a0 = 0.f, a1 = 0.f, a2 = 0.f, a3 = 0.f;
    for (int j = 0; j < H_; j += 4) {
        float4 w4 = *(const float4*)(wr + j);
        a0 += w4.x * x[j + 0];
        a1 += w4.y * x[j + 1];
        a2 += w4.z * x[j + 2];
        a3 += w4.w * x[j + 3];
    }
    d_logit0[k * B_ + b] = (a0 + a1) + (a2 + a3) + b_out[k];
}

// -------------- pre-projection SGEMM: C[m][n], m = b*256+t -------------------
__global__ void __launch_bounds__(256) k_pre(const float* __restrict__ A,
                                             const float* __restrict__ W,
                                             const float* __restrict__ bih,
                                             const float* __restrict__ bhh) {
    __shared__ float As[8][132];
    __shared__ float Bs[8][132];
    int tid = threadIdx.x;
    int m0 = blockIdx.y * 128;
    int n0 = blockIdx.x * 128;
    int lr = tid >> 1;
    int lc = (tid & 1) * 4;
    int ty = tid >> 4;
    int tx = tid & 15;

    float acc[8][8];
#pragma unroll
    for (int i = 0; i < 8; i++)
#pragma unroll
        for (int j = 0; j < 8; j++) acc[i][j] = 0.f;

    for (int kt = 0; kt < D_; kt += 8) {
        float4 a = *(const float4*)&A[(size_t)(m0 + lr) * D_ + kt + lc];
        As[lc + 0][lr] = a.x; As[lc + 1][lr] = a.y;
        As[lc + 2][lr] = a.z; As[lc + 3][lr] = a.w;
        float4 b = *(const float4*)&W[(size_t)(n0 + lr) * (D_ + K_) + kt + lc];
        Bs[lc + 0][lr] = b.x; Bs[lc + 1][lr] = b.y;
        Bs[lc + 2][lr] = b.z; Bs[lc + 3][lr] = b.w;
        __syncthreads();
#pragma unroll
        for (int k = 0; k < 8; k++) {
            float ra[8], rb[8];
            *(float4*)&ra[0] = *(const float4*)&As[k][ty * 4];
            *(float4*)&ra[4] = *(const float4*)&As[k][64 + ty * 4];
            *(float4*)&rb[0] = *(const float4*)&Bs[k][tx * 4];
            *(float4*)&rb[4] = *(const float4*)&Bs[k][64 + tx * 4];
#pragma unroll
            for (int i = 0; i < 8; i++)
#pragma unroll
                for (int j = 0; j < 8; j++) acc[i][j] += ra[i] * rb[j];
        }
        __syncthreads();
    }

#pragma unroll
    for (int i = 0; i < 8; i++) {
        int m = m0 + ((i < 4) ? (ty * 4 + i) : (64 + ty * 4 + i - 4));
        int tt = m & 255;
        int bb = m >> 8;
#pragma unroll
        for (int j = 0; j < 8; j++) {
            int n = n0 + ((j < 4) ? (tx * 4 + j) : (64 + tx * 4 + j - 4));
            d_pre0[((size_t)tt * R_ + n) * B_ + bb] = acc[i][j] + bih[n] + bhh[n];
        }
    }
}

// ------------------------- persistent recurrence -----------------------------
// 128 CTAs x 256 threads. CTA c owns hidden units u = c*4 .. c*4+3 for both
// LSTM layers (16 gate rows each, local row r = g*4+ul) and tag row c.
// Weights k-major in SMEM: w0s[k*16+r], w1s[k*16+r]. lane = batch everywhere.
__global__ void __launch_bounds__(256, 1) k_loop(const float* __restrict__ W_out,
                                                 const float* __restrict__ b_out) {
    extern __shared__ float smem[];
    float* w0s     = smem;                    // 640*16  = 10240
    float* w1s     = w0s + KC0 * 16;          // 1024*16 = 16384
    float* wout    = w1s + KC1 * 16;          // 512
    float* bias1s  = wout + 512;              // 16
    float* smx     = bias1s + 32;             // 128*33 = 4224  (pad bias1s to 32)
    float* partial = smx + 128 * 33;          // 8*16*32 = 4096
    float* pout    = partial + 4096;          // 8*32 = 256

    const int c    = blockIdx.x;
    const int tid  = threadIdx.x;
    const int lane = tid & 31;
    const int w    = tid >> 5;                // 8 warps

    // ---- stage weights into SMEM (once) ----
#pragma unroll
    for (int r = 0; r < 16; r++) {
        int grow = (r >> 2) * H_ + c * 4 + (r & 3);
        const float* src0 = d_W0 + (size_t)grow * KC0;
        for (int k = tid; k < KC0; k += 256) w0s[k * 16 + r] = src0[k];
        const float* src1 = d_W1 + (size_t)grow * KC1;
        for (int k = tid; k < KC1; k += 256) w1s[k * 16 + r] = src1[k];
        if (tid == 0) bias1s[r] = d_bias1[grow];
    }
    for (int j = tid; j < H_; j += 256) wout[j] = W_out[(size_t)c * H_ + j];
    __syncthreads();

    // ---- per-thread cell state (tid<128): b = tid&31, ul = tid>>5 ----
    float c1_reg = 0.f, c2_reg = 0.f;
    int b = tid & 31, ul = tid >> 5;          // ul 0..7; only ul<4 used
    int u = c * 4 + (ul & 3);
    if (tid < 128) {
        c1_reg = d_c1[u * 32 + b];
        c2_reg = d_c2[u * 32 + b];
    }
    float bout_c = b_out[c];

    unsigned gen = *(volatile unsigned*)&g_bargen;

    for (int t = 0; t < T_; t++) {
        const int old = t & 1, nw = old ^ 1;
        const float* __restrict__ h1old = d_h1 + old * (H_ * B_);
        float*       __restrict__ h1new = d_h1 + nw  * (H_ * B_);
        const float* __restrict__ h2old = d_h2 + old * (H_ * B_);
        float*       __restrict__ h2new = d_h2 + nw  * (H_ * B_);

        // prefetch pre0 gate terms for this CTA's units (hidden by dot below)
        float pre[4];
        if (tid < 128 && ul < 4) {
#pragma unroll
            for (int g = 0; g < 4; g++)
                pre[g] = __ldcg(&d_pre0[((size_t)t * R_ + g * H_ + u) * B_ + b]);
        }

        // ---- stage prev logits coalesced, then softmax into smx[k*33+b] ----
        {
            const float* lg = (t == 0) ? d_logit0
                                       : d_logits + (size_t)(t - 1) * K_ * B_;
#pragma unroll
            for (int kk = 0; kk < 16; kk++) {
                int k = w * 16 + kk;
                smx[k * 33 + lane] = __ldcg(lg + k * 32 + lane);
            }
        }
        __syncthreads();
        {
            // warp w normalizes batches b4..b4+3; lanes index tags
            int b4 = w * 4;
#pragma unroll
            for (int bb = 0; bb < 4; bb++) {
                int bq = b4 + bb;
                float v[4];
#pragma unroll
                for (int i = 0; i < 4; i++) v[i] = smx[(lane + 32 * i) * 33 + bq];
                float mx = fmaxf(fmaxf(v[0], v[1]), fmaxf(v[2], v[3]));
#pragma unroll
                for (int o = 16; o > 0; o >>= 1)
                    mx = fmaxf(mx, __shfl_xor_sync(~0u, mx, o));
                float s = 0.f;
#pragma unroll
                for (int i = 0; i < 4; i++) { v[i] = __expf(v[i] - mx); s += v[i]; }
#pragma unroll
                for (int o = 16; o > 0; o >>= 1) s += __shfl_xor_sync(~0u, s, o);
                float inv = 1.0f / s;
#pragma unroll
                for (int i = 0; i < 4; i++) smx[(lane + 32 * i) * 33 + bq] = v[i] * inv;
            }
        }
        __syncthreads();

        // =================== cell0 dot: 16 rows, k-sliced =====================
        {
            unsigned long long acc[8];
#pragma unroll
            for (int p = 0; p < 8; p++) acc[p] = 0ull;

            int kb = w * 64;
#pragma unroll 16
            for (int kk = 0; kk < 64; kk++) {
                int k = kb + kk;
                unsigned long long xx = pk2(__ldcg(h1old + k * 32 + lane));
                const ulonglong2* q = (const ulonglong2*)(w0s + k * 16);
                ulonglong2 q0 = q[0], q1 = q[1], q2 = q[2], q3 = q[3];
                fma2(acc[0], xx, q0.x); fma2(acc[1], xx, q0.y);
                fma2(acc[2], xx, q1.x); fma2(acc[3], xx, q1.y);
                fma2(acc[4], xx, q2.x); fma2(acc[5], xx, q2.y);
                fma2(acc[6], xx, q3.x); fma2(acc[7], xx, q3.y);
            }
            int kb2 = w * 16;
#pragma unroll
            for (int kk = 0; kk < 16; kk++) {
                int k = H_ + kb2 + kk;
                unsigned long long xx = pk2(smx[(kb2 + kk) * 33 + lane]);
                const ulonglong2* q = (const ulonglong2*)(w0s + k * 16);
                ulonglong2 q0 = q[0], q1 = q[1], q2 = q[2], q3 = q[3];
                fma2(acc[0], xx, q0.x); fma2(acc[1], xx, q0.y);
                fma2(acc[2], xx, q1.x); fma2(acc[3], xx, q1.y);
                fma2(acc[4], xx, q2.x); fma2(acc[5], xx, q2.y);
                fma2(acc[6], xx, q3.x); fma2(acc[7], xx, q3.y);
            }
#pragma unroll
            for (int p = 0; p < 8; p++) {
                float lo, hi; unpk2(lo, hi, acc[p]);
                partial[(w * 16 + 2 * p + 0) * 32 + lane] = lo;
                partial[(w * 16 + 2 * p + 1) * 32 + lane] = hi;
            }
        }
        __syncthreads();

        if (tid < 128 && ul < 4) {
            float gate[4];
#pragma unroll
            for (int g = 0; g < 4; g++) {
                int r = g * 4 + ul;
                float s = pre[g];
#pragma unroll
                for (int w2 = 0; w2 < 8; w2++) s += partial[(w2 * 16 + r) * 32 + b];
                gate[g] = s;
            }
            float iv = sigf(gate[0]);
            float fv = sigf(gate[1]);
            float gv = tanhf(gate[2]);
            float ov = sigf(gate[3]);
            c1_reg = fv * c1_reg + iv * gv;
            h1new[u * 32 + b] = ov * tanhf(c1_reg);
        }
        gbar(gen);

        // =================== cell1 dot: 16 rows, k = [h1new; h2old] ==========
        {
            unsigned long long acc[8];
#pragma unroll
            for (int p = 0; p < 8; p++) acc[p] = 0ull;

            int kb = w * 64;
#pragma unroll 16
            for (int kk = 0; kk < 64; kk++) {
                int k = kb + kk;
                unsigned long long xx = pk2(__ldcg(h1new + k * 32 + lane));
                const ulonglong2* q = (const ulonglong2*)(w1s + k * 16);
                ulonglong2 q0 = q[0], q1 = q[1], q2 = q[2], q3 = q[3];
                fma2(acc[0], xx, q0.x); fma2(acc[1], xx, q0.y);
                fma2(acc[2], xx, q1.x); fma2(acc[3], xx, q1.y);
                fma2(acc[4], xx, q2.x); fma2(acc[5], xx, q2.y);
                fma2(acc[6], xx, q3.x); fma2(acc[7], xx, q3.y);
            }
#pragma unroll 16
            for (int kk = 0; kk < 64; kk++) {
                int k = H_ + kb + kk;
                unsigned long long xx = pk2(__ldcg(h2old + (kb + kk) * 32 + lane));
                const ulonglong2* q = (const ulonglong2*)(w1s + k * 16);
                ulonglong2 q0 = q[0], q1 = q[1], q2 = q[2], q3 = q[3];
                fma2(acc[0], xx, q0.x); fma2(acc[1], xx, q0.y);
                fma2(acc[2], xx, q1.x); fma2(acc[3], xx, q1.y);
                fma2(acc[4], xx, q2.x); fma2(acc[5], xx, q2.y);
                fma2(acc[6], xx, q3.x); fma2(acc[7], xx, q3.y);
            }
#pragma unroll
            for (int p = 0; p < 8; p++) {
                float lo, hi; unpk2(lo, hi, acc[p]);
                partial[(w * 16 + 2 * p + 0) * 32 + lane] = lo;
                partial[(w * 16 + 2 * p + 1) * 32 + lane] = hi;
            }
        }
        __syncthreads();

        if (tid < 128 && ul < 4) {
            float gate[4];
#pragma unroll
            for (int g = 0; g < 4; g++) {
                int r = g * 4 + ul;
                float s = bias1s[r];
#pragma unroll
                for (int w2 = 0; w2 < 8; w2++) s += partial[(w2 * 16 + r) * 32 + b];
                gate[g] = s;
            }
            float iv = sigf(gate[0]);
            float fv = sigf(gate[1]);
            float gv = tanhf(gate[2]);
            float ov = sigf(gate[3]);
            c2_reg = fv * c2_reg + iv * gv;
            h2new[u * 32 + b] = ov * tanhf(c2_reg);
        }
        gbar(gen);

        // =================== out: tag row c, j-sliced =========================
        {
            float a = 0.f;
            int jb = w * 64;
#pragma unroll 16
            for (int jj = 0; jj < 64; jj++) {
                int j = jb + jj;
                a += wout[j] * __ldcg(h2new + j * 32 + lane);
            }
            pout[w * 32 + lane] = a;
        }
        __syncthreads();
        if (tid < 32) {
            float s = bout_c;
#pragma unroll
            for (int w2 = 0; w2 < 8; w2++) s += pout[w2 * 32 + tid];
            d_logits[((size_t)t * K_ + c) * 32 + tid] = s;
        }
        gbar(gen);
    }
}

// --------------------------- final masked softmax ----------------------------
__global__ void __launch_bounds__(256) k_final(const float* __restrict__ mask,
                                               float* __restrict__ out) {
    int tid = threadIdx.x, lane = tid & 31, w = tid >> 5;
    int gidx = blockIdx.x * 8 + w;             // 0..8191
    int b = gidx >> 8, t = gidx & 255;
    float pen = (1.0f - mask[b * T_ + t]) * -1e32f;
    float v[4];
#pragma unroll
    for (int i = 0; i < 4; i++)
        v[i] = d_logits[((size_t)t * K_ + lane + 32 * i) * B_ + b] + pen;
    float mx = fmaxf(fmaxf(v[0], v[1]), fmaxf(v[2], v[3]));
#pragma unroll
    for (int o = 16; o > 0; o >>= 1) mx = fmaxf(mx, __shfl_xor_sync(~0u, mx, o));
    float s = 0.f;
#pragma unroll
    for (int i = 0; i < 4; i++) { v[i] = __expf(v[i] - mx); s += v[i]; }
#pragma unroll
    for (int o = 16; o > 0; o >>= 1) s += __shfl_xor_sync(~0u, s, o);
    float inv = 1.0f / s;
#pragma unroll
    for (int i = 0; i < 4; i++)
        out[((size_t)b * T_ + t) * K_ + lane + 32 * i] = v[i] * inv;
}

// ----------------------------------------------------------------------------
extern "C" void kernel_launch(void* const* d_in, const int* in_sizes, int n_in,
                              void* d_out, int out_size) {
    const float* hiddens = (const float*)d_in[0];
    const float* h_t     = (const float*)d_in[1];
    const float* c_t     = (const float*)d_in[2];
    const float* mask    = (const float*)d_in[3];
    const float* W_out   = (const float*)d_in[4];
    const float* b_out   = (const float*)d_in[5];
    const float* W_ih0   = (const float*)d_in[6];
    const float* W_hh0   = (const float*)d_in[7];
    const float* b_ih0   = (const float*)d_in[8];
    const float* b_hh0   = (const float*)d_in[9];
    const float* W_ih1   = (const float*)d_in[10];
    const float* W_hh1   = (const float*)d_in[11];
    const float* b_ih1   = (const float*)d_in[12];
    const float* b_hh1   = (const float*)d_in[13];
    float* out = (float*)d_out;

    // SMEM: w0s 10240 + w1s 16384 + wout 512 + bias1s 32 + smx 4224
    //       + partial 4096 + pout 256 = 35744 floats = 142976 bytes
    const int SMEM_LOOP = 35744 * 4;
    cudaFuncSetAttribute(k_loop, cudaFuncAttributeMaxDynamicSharedMemorySize, SMEM_LOOP);

    k_pack<<<R_, 256>>>(W_ih0, W_hh0, W_ih1, W_hh1, b_ih1, b_hh1);
    k_init<<<64, 256>>>(h_t, c_t);
    k_initsm<<<B_, K_>>>(hiddens, W_out, b_out);
    k_pre<<<dim3(16, 64), 256>>>(hiddens, W_ih0, b_ih0, b_hh0);

    k_loop<<<G_, 256, SMEM_LOOP>>>(W_out, b_out);

    k_final<<<1024, 256>>>(mask, out);
}

// round 4
// speedup vs baseline: 2.9338x; 1.1159x over previous
#include <cuda_runtime.h>
#include <cuda_bf16.h>
#include <cstdint>
#include <cstddef>

// ---------------------------------------------------------------------------
// TaggingFNNDecoder: 2-layer LSTM tag decoder. B=32, T=256, D=1024, H=512, K=128
// Round 3: flag-array grid barrier + 512-thread persistent CTAs + FFMA2 k_pre.
// ---------------------------------------------------------------------------

#define B_  32
#define T_  256
#define D_  1024
#define H_  512
#define K_  128
#define R_  2048    // 4*H gate rows
#define KC0 640     // cell0 reduced k-dim: h1(512) + sm(128)
#define KC1 1024    // cell1 k-dim: h1(512) + h2(512)
#define G_  128     // persistent grid size (<= 148 SMs, 1 CTA/SM)

// ------------------------- device scratch ----------------------------------
__device__ float d_pre0[(size_t)T_ * R_ * B_];   // 64 MB [t][row][b]
__device__ float d_W0[(size_t)R_ * KC0];         // [row][ W_hh0 | W_ih0[:,1024:] ]
__device__ float d_W1[(size_t)R_ * KC1];         // [row][ W_ih1 | W_hh1 ]
__device__ float d_bias1[R_];
__device__ float d_h1[2 * H_ * B_];              // double buffered [j][b]
__device__ float d_h2[2 * H_ * B_];
__device__ float d_c1[H_ * B_];
__device__ float d_c2[H_ * B_];
__device__ float d_logit0[K_ * B_];              // [k][b] initial tag logits
__device__ float d_logits[(size_t)T_ * K_ * B_]; // [t][k][b] raw logits

// flag-array barrier state: one flag per CTA, 128B stride (distinct L2 lines)
__device__ volatile unsigned g_flags[G_ * 32];

__device__ __forceinline__ float sigf(float x) {
    return 1.0f / (1.0f + __expf(-x));
}

// packed fp32x2 helpers
__device__ __forceinline__ unsigned long long pk2(float x) {
    unsigned long long r; unsigned u = __float_as_uint(x);
    asm("mov.b64 %0, {%1, %1};" : "=l"(r) : "r"(u));
    return r;
}
__device__ __forceinline__ void fma2(unsigned long long& a,
                                     unsigned long long x, unsigned long long w) {
    asm("fma.rn.f32x2 %0, %1, %2, %0;" : "+l"(a) : "l"(x), "l"(w));
}
__device__ __forceinline__ void unpk2(float& lo, float& hi, unsigned long long v) {
    unsigned l, h;
    asm("mov.b64 {%0, %1}, %2;" : "=r"(l), "=r"(h) : "l"(v));
    lo = __uint_as_float(l); hi = __uint_as_float(h);
}

// grid barrier: each CTA publishes a monotonically increasing flag; lanes
// 0..G_-1 each poll one (spread) flag. release = threadfence + volatile store;
// acquire = threadfence after observing flags, then __syncthreads.
__device__ __forceinline__ void gbar(unsigned target) {
    __syncthreads();
    if (threadIdx.x == 0) {
        __threadfence();
        g_flags[blockIdx.x * 32] = target;
    }
    if (threadIdx.x < G_) {
        while (g_flags[threadIdx.x * 32] < target) {}
        __threadfence();
    }
    __syncthreads();
}

// ----------------------------- weight repack --------------------------------
__global__ void k_pack(const float* __restrict__ Wih0, const float* __restrict__ Whh0,
                       const float* __restrict__ Wih1, const float* __restrict__ Whh1,
                       const float* __restrict__ bih1, const float* __restrict__ bhh1) {
    int row = blockIdx.x;          // 0..2047
    int tid = threadIdx.x;         // 256 threads
    const float4* s1 = (const float4*)(Whh0 + (size_t)row * H_);
    float4* dW0 = (float4*)(d_W0 + (size_t)row * KC0);
    for (int i = tid; i < H_ / 4; i += 256) dW0[i] = s1[i];
    const float4* s2 = (const float4*)(Wih0 + (size_t)row * (D_ + K_) + D_);
    for (int i = tid; i < K_ / 4; i += 256) dW0[H_ / 4 + i] = s2[i];
    float4* dW1 = (float4*)(d_W1 + (size_t)row * KC1);
    const float4* s3 = (const float4*)(Wih1 + (size_t)row * H_);
    const float4* s4 = (const float4*)(Whh1 + (size_t)row * H_);
    for (int i = tid; i < H_ / 4; i += 256) { dW1[i] = s3[i]; dW1[H_ / 4 + i] = s4[i]; }
    if (tid == 0) d_bias1[row] = bih1[row] + bhh1[row];
}

// ----------------------------- state init -----------------------------------
__global__ void k_init(const float* __restrict__ h_t, const float* __restrict__ c_t) {
    int idx = blockIdx.x * blockDim.x + threadIdx.x;   // 0..16383 = j*32+b
    if (idx < G_ * 32) g_flags[idx] = 0;               // reset barrier flags
    if (idx < H_ * B_) {
        int j = idx >> 5, b = idx & 31;
        d_h1[idx] = h_t[b * H_ + j];                   // layer0, buffer 0
        d_h2[idx] = h_t[B_ * H_ + b * H_ + j];         // layer1, buffer 0
        d_c1[idx] = c_t[b * H_ + j];
        d_c2[idx] = c_t[B_ * H_ + b * H_ + j];
    }
}

// ------------------- initial tag logits (raw, no softmax) -------------------
__global__ void k_initsm(const float* __restrict__ hid, const float* __restrict__ W_out,
                         const float* __restrict__ b_out) {
    int b = blockIdx.x;            // 32 blocks
    int k = threadIdx.x;           // 128 threads
    const float* x  = hid + (size_t)b * T_ * D_;       // hiddens[b][0][:]
    const float* wr = W_out + (size_t)k * H_;
    float a0 = 0.f, a1 = 0.f, a2 = 0.f, a3 = 0.f;
    for (int j = 0; j < H_; j += 4) {
        float4 w4 = *(const float4*)(wr + j);
        a0 += w4.x * x[j + 0];
        a1 += w4.y * x[j + 1];
        a2 += w4.z * x[j + 2];
        a3 += w4.w * x[j + 3];
    }
    d_logit0[k * B_ + b] = (a0 + a1) + (a2 + a3) + b_out[k];
}

// -------------- pre-projection SGEMM (FFMA2): C[m][n], m = b*256+t -----------
__global__ void __launch_bounds__(256) k_pre(const float* __restrict__ A,
                                             const float* __restrict__ W,
                                             const float* __restrict__ bih,
                                             const float* __restrict__ bhh) {
    __shared__ float As[8][132];
    __shared__ float Bs[8][132];
    int tid = threadIdx.x;
    int m0 = blockIdx.y * 128;
    int n0 = blockIdx.x * 128;
    int lr = tid >> 1;
    int lc = (tid & 1) * 4;
    int ty = tid >> 4;
    int tx = tid & 15;

    unsigned long long acc2[8][4];
#pragma unroll
    for (int i = 0; i < 8; i++)
#pragma unroll
        for (int j = 0; j < 4; j++) acc2[i][j] = 0ull;

    for (int kt = 0; kt < D_; kt += 8) {
        float4 a = *(const float4*)&A[(size_t)(m0 + lr) * D_ + kt + lc];
        As[lc + 0][lr] = a.x; As[lc + 1][lr] = a.y;
        As[lc + 2][lr] = a.z; As[lc + 3][lr] = a.w;
        float4 b = *(const float4*)&W[(size_t)(n0 + lr) * (D_ + K_) + kt + lc];
        Bs[lc + 0][lr] = b.x; Bs[lc + 1][lr] = b.y;
        Bs[lc + 2][lr] = b.z; Bs[lc + 3][lr] = b.w;
        __syncthreads();
#pragma unroll
        for (int k = 0; k < 8; k++) {
            float4 raA = *(const float4*)&As[k][ty * 4];
            float4 raB = *(const float4*)&As[k][64 + ty * 4];
            ulonglong2 rbA = *(const ulonglong2*)&Bs[k][tx * 4];
            ulonglong2 rbB = *(const ulonglong2*)&Bs[k][64 + tx * 4];
            float ra[8] = {raA.x, raA.y, raA.z, raA.w, raB.x, raB.y, raB.z, raB.w};
#pragma unroll
            for (int i = 0; i < 8; i++) {
                unsigned long long ax = pk2(ra[i]);
                fma2(acc2[i][0], ax, rbA.x);
                fma2(acc2[i][1], ax, rbA.y);
                fma2(acc2[i][2], ax, rbB.x);
                fma2(acc2[i][3], ax, rbB.y);
            }
        }
        __syncthreads();
    }

#pragma unroll
    for (int i = 0; i < 8; i++) {
        int m = m0 + ((i < 4) ? (ty * 4 + i) : (64 + ty * 4 + i - 4));
        int tt = m & 255;
        int bb = m >> 8;
#pragma unroll
        for (int j2 = 0; j2 < 4; j2++) {
            float lo, hi;
            unpk2(lo, hi, acc2[i][j2]);
            int nb = (j2 < 2) ? (n0 + tx * 4 + j2 * 2)
                              : (n0 + 64 + tx * 4 + (j2 - 2) * 2);
            d_pre0[((size_t)tt * R_ + nb + 0) * B_ + bb] = lo + bih[nb] + bhh[nb];
            d_pre0[((size_t)tt * R_ + nb + 1) * B_ + bb] = hi + bih[nb + 1] + bhh[nb + 1];
        }
    }
}

// ------------------------- persistent recurrence -----------------------------
// 128 CTAs x 512 threads (16 warps). CTA c owns hidden units u = c*4..c*4+3 for
// both LSTM layers (16 gate rows each, local row r = g*4+ul) and tag row c.
// Weights k-major in SMEM: w0s[k*16+r], w1s[k*16+r]. lane = batch everywhere.
__global__ void __launch_bounds__(512, 1) k_loop(const float* __restrict__ W_out,
                                                 const float* __restrict__ b_out) {
    extern __shared__ float smem[];
    float* w0s     = smem;                    // 640*16  = 10240
    float* w1s     = w0s + KC0 * 16;          // 1024*16 = 16384
    float* wout    = w1s + KC1 * 16;          // 512
    float* bias1s  = wout + 512;              // 16 (padded to 32)
    float* smx     = bias1s + 32;             // 128*33 = 4224
    float* partial = smx + 128 * 33;          // 16*16*32 = 8192
    float* pout    = partial + 8192;          // 16*32 = 512

    const int c    = blockIdx.x;
    const int tid  = threadIdx.x;
    const int lane = tid & 31;
    const int w    = tid >> 5;                // 16 warps

    // ---- stage weights into SMEM (once) ----
#pragma unroll
    for (int r = 0; r < 16; r++) {
        int grow = (r >> 2) * H_ + c * 4 + (r & 3);
        const float* src0 = d_W0 + (size_t)grow * KC0;
        for (int k = tid; k < KC0; k += 512) w0s[k * 16 + r] = src0[k];
        const float* src1 = d_W1 + (size_t)grow * KC1;
        for (int k = tid; k < KC1; k += 512) w1s[k * 16 + r] = src1[k];
        if (tid == 0) bias1s[r] = d_bias1[grow];
    }
    for (int j = tid; j < H_; j += 512) wout[j] = W_out[(size_t)c * H_ + j];
    __syncthreads();

    // ---- per-thread cell state (tid<128): b = tid&31, ul = tid>>5 ----
    float c1_reg = 0.f, c2_reg = 0.f;
    int b = tid & 31, ul = tid >> 5;          // ul 0..15; only ul<4 used
    int u = c * 4 + (ul & 3);
    if (tid < 128) {
        c1_reg = d_c1[u * 32 + b];
        c2_reg = d_c2[u * 32 + b];
    }
    float bout_c = b_out[c];

    unsigned tgt = 1;

    for (int t = 0; t < T_; t++) {
        const int old = t & 1, nw = old ^ 1;
        const float* __restrict__ h1old = d_h1 + old * (H_ * B_);
        float*       __restrict__ h1new = d_h1 + nw  * (H_ * B_);
        const float* __restrict__ h2old = d_h2 + old * (H_ * B_);
        float*       __restrict__ h2new = d_h2 + nw  * (H_ * B_);

        // prefetch pre0 gate terms (hidden under softmax + cell0 dot)
        float pre[4];
        if (tid < 128) {
#pragma unroll
            for (int g = 0; g < 4; g++)
                pre[g] = __ldcg(&d_pre0[((size_t)t * R_ + g * H_ + u) * B_ + b]);
        }

        // ---- stage prev logits coalesced, then softmax into smx[k*33+b] ----
        {
            const float* lg = (t == 0) ? d_logit0
                                       : d_logits + (size_t)(t - 1) * K_ * B_;
#pragma unroll
            for (int kk = 0; kk < 8; kk++) {
                int k = w * 8 + kk;
                smx[k * 33 + lane] = __ldcg(lg + k * 32 + lane);
            }
        }
        __syncthreads();
        {
            // warp w normalizes batches 2w, 2w+1; lanes index tags
#pragma unroll
            for (int bb = 0; bb < 2; bb++) {
                int bq = w * 2 + bb;
                float v[4];
#pragma unroll
                for (int i = 0; i < 4; i++) v[i] = smx[(lane + 32 * i) * 33 + bq];
                float mx = fmaxf(fmaxf(v[0], v[1]), fmaxf(v[2], v[3]));
#pragma unroll
                for (int o = 16; o > 0; o >>= 1)
                    mx = fmaxf(mx, __shfl_xor_sync(~0u, mx, o));
                float s = 0.f;
#pragma unroll
                for (int i = 0; i < 4; i++) { v[i] = __expf(v[i] - mx); s += v[i]; }
#pragma unroll
                for (int o = 16; o > 0; o >>= 1) s += __shfl_xor_sync(~0u, s, o);
                float inv = 1.0f / s;
#pragma unroll
                for (int i = 0; i < 4; i++) smx[(lane + 32 * i) * 33 + bq] = v[i] * inv;
            }
        }
        __syncthreads();

        // =================== cell0 dot: 16 rows, k-sliced over 16 warps ======
        {
            unsigned long long acc[8];
#pragma unroll
            for (int p = 0; p < 8; p++) acc[p] = 0ull;

            int kb = w * 32;
#pragma unroll 16
            for (int kk = 0; kk < 32; kk++) {
                int k = kb + kk;
                unsigned long long xx = pk2(__ldcg(h1old + k * 32 + lane));
                const ulonglong2* q = (const ulonglong2*)(w0s + k * 16);
                ulonglong2 q0 = q[0], q1 = q[1], q2 = q[2], q3 = q[3];
                fma2(acc[0], xx, q0.x); fma2(acc[1], xx, q0.y);
                fma2(acc[2], xx, q1.x); fma2(acc[3], xx, q1.y);
                fma2(acc[4], xx, q2.x); fma2(acc[5], xx, q2.y);
                fma2(acc[6], xx, q3.x); fma2(acc[7], xx, q3.y);
            }
            int kb2 = w * 8;
#pragma unroll
            for (int kk = 0; kk < 8; kk++) {
                int k = H_ + kb2 + kk;
                unsigned long long xx = pk2(smx[(kb2 + kk) * 33 + lane]);
                const ulonglong2* q = (const ulonglong2*)(w0s + k * 16);
                ulonglong2 q0 = q[0], q1 = q[1], q2 = q[2], q3 = q[3];
                fma2(acc[0], xx, q0.x); fma2(acc[1], xx, q0.y);
                fma2(acc[2], xx, q1.x); fma2(acc[3], xx, q1.y);
                fma2(acc[4], xx, q2.x); fma2(acc[5], xx, q2.y);
                fma2(acc[6], xx, q3.x); fma2(acc[7], xx, q3.y);
            }
#pragma unroll
            for (int p = 0; p < 8; p++) {
                float lo, hi; unpk2(lo, hi, acc[p]);
                partial[(w * 16 + 2 * p + 0) * 32 + lane] = lo;
                partial[(w * 16 + 2 * p + 1) * 32 + lane] = hi;
            }
        }
        __syncthreads();

        if (tid < 128) {
            float gate[4];
#pragma unroll
            for (int g = 0; g < 4; g++) {
                int r = g * 4 + ul;
                float s = pre[g];
#pragma unroll
                for (int w2 = 0; w2 < 16; w2++) s += partial[(w2 * 16 + r) * 32 + b];
                gate[g] = s;
            }
            float iv = sigf(gate[0]);
            float fv = sigf(gate[1]);
            float gv = tanhf(gate[2]);
            float ov = sigf(gate[3]);
            c1_reg = fv * c1_reg + iv * gv;
            h1new[u * 32 + b] = ov * tanhf(c1_reg);
        }
        gbar(tgt++);

        // =================== cell1 dot: 16 rows, k = [h1new; h2old] ==========
        {
            unsigned long long acc[8];
#pragma unroll
            for (int p = 0; p < 8; p++) acc[p] = 0ull;

            // warps 0..7 -> h1new slice, warps 8..15 -> h2old slice
            const float* __restrict__ xsrc =
                (w < 8) ? (h1new + (w * 64) * 32) : (h2old + ((w - 8) * 64) * 32);
            const float* wbase = w1s + (w * 64) * 16;
#pragma unroll 16
            for (int kk = 0; kk < 64; kk++) {
                unsigned long long xx = pk2(__ldcg(xsrc + kk * 32 + lane));
                const ulonglong2* q = (const ulonglong2*)(wbase + kk * 16);
                ulonglong2 q0 = q[0], q1 = q[1], q2 = q[2], q3 = q[3];
                fma2(acc[0], xx, q0.x); fma2(acc[1], xx, q0.y);
                fma2(acc[2], xx, q1.x); fma2(acc[3], xx, q1.y);
                fma2(acc[4], xx, q2.x); fma2(acc[5], xx, q2.y);
                fma2(acc[6], xx, q3.x); fma2(acc[7], xx, q3.y);
            }
#pragma unroll
            for (int p = 0; p < 8; p++) {
                float lo, hi; unpk2(lo, hi, acc[p]);
                partial[(w * 16 + 2 * p + 0) * 32 + lane] = lo;
                partial[(w * 16 + 2 * p + 1) * 32 + lane] = hi;
            }
        }
        __syncthreads();

        if (tid < 128) {
            float gate[4];
#pragma unroll
            for (int g = 0; g < 4; g++) {
                int r = g * 4 + ul;
                float s = bias1s[r];
#pragma unroll
                for (int w2 = 0; w2 < 16; w2++) s += partial[(w2 * 16 + r) * 32 + b];
                gate[g] = s;
            }
            float iv = sigf(gate[0]);
            float fv = sigf(gate[1]);
            float gv = tanhf(gate[2]);
            float ov = sigf(gate[3]);
            c2_reg = fv * c2_reg + iv * gv;
            h2new[u * 32 + b] = ov * tanhf(c2_reg);
        }
        gbar(tgt++);

        // =================== out: tag row c, j-sliced over 16 warps ==========
        {
            float a = 0.f;
            int jb = w * 32;
#pragma unroll 16
            for (int jj = 0; jj < 32; jj++) {
                int j = jb + jj;
                a += wout[j] * __ldcg(h2new + j * 32 + lane);
            }
            pout[w * 32 + lane] = a;
        }
        __syncthreads();
        if (tid < 32) {
            float s = bout_c;
#pragma unroll
            for (int w2 = 0; w2 < 16; w2++) s += pout[w2 * 32 + tid];
            d_logits[((size_t)t * K_ + c) * 32 + tid] = s;
        }
        gbar(tgt++);
    }
}

// --------------------------- final masked softmax ----------------------------
__global__ void __launch_bounds__(256) k_final(const float* __restrict__ mask,
                                               float* __restrict__ out) {
    int tid = threadIdx.x, lane = tid & 31, w = tid >> 5;
    int gidx = blockIdx.x * 8 + w;             // 0..8191
    int b = gidx >> 8, t = gidx & 255;
    float pen = (1.0f - mask[b * T_ + t]) * -1e32f;
    float v[4];
#pragma unroll
    for (int i = 0; i < 4; i++)
        v[i] = d_logits[((size_t)t * K_ + lane + 32 * i) * B_ + b] + pen;
    float mx = fmaxf(fmaxf(v[0], v[1]), fmaxf(v[2], v[3]));
#pragma unroll
    for (int o = 16; o > 0; o >>= 1) mx = fmaxf(mx, __shfl_xor_sync(~0u, mx, o));
    float s = 0.f;
#pragma unroll
    for (int i = 0; i < 4; i++) { v[i] = __expf(v[i] - mx); s += v[i]; }
#pragma unroll
    for (int o = 16; o > 0; o >>= 1) s += __shfl_xor_sync(~0u, s, o);
    float inv = 1.0f / s;
#pragma unroll
    for (int i = 0; i < 4; i++)
        out[((size_t)b * T_ + t) * K_ + lane + 32 * i] = v[i] * inv;
}

// ----------------------------------------------------------------------------
extern "C" void kernel_launch(void* const* d_in, const int* in_sizes, int n_in,
                              void* d_out, int out_size) {
    const float* hiddens = (const float*)d_in[0];
    const float* h_t     = (const float*)d_in[1];
    const float* c_t     = (const float*)d_in[2];
    const float* mask    = (const float*)d_in[3];
    const float* W_out   = (const float*)d_in[4];
    const float* b_out   = (const float*)d_in[5];
    const float* W_ih0   = (const float*)d_in[6];
    const float* W_hh0   = (const float*)d_in[7];
    const float* b_ih0   = (const float*)d_in[8];
    const float* b_hh0   = (const float*)d_in[9];
    const float* W_ih1   = (const float*)d_in[10];
    const float* W_hh1   = (const float*)d_in[11];
    const float* b_ih1   = (const float*)d_in[12];
    const float* b_hh1   = (const float*)d_in[13];
    float* out = (float*)d_out;

    // SMEM: w0s 10240 + w1s 16384 + wout 512 + bias1s 32 + smx 4224
    //       + partial 8192 + pout 512 = 40096 floats = 160384 bytes
    const int SMEM_LOOP = 40096 * 4;
    cudaFuncSetAttribute(k_loop, cudaFuncAttributeMaxDynamicSharedMemorySize, SMEM_LOOP);

    k_pack<<<R_, 256>>>(W_ih0, W_hh0, W_ih1, W_hh1, b_ih1, b_hh1);
    k_init<<<64, 256>>>(h_t, c_t);
    k_initsm<<<B_, K_>>>(hiddens, W_out, b_out);
    k_pre<<<dim3(16, 64), 256>>>(hiddens, W_ih0, b_ih0, b_hh0);

    k_loop<<<G_, 512, SMEM_LOOP>>>(W_out, b_out);

    k_final<<<1024, 256>>>(mask, out);
}

// round 5
// speedup vs baseline: 3.3759x; 1.1507x over previous
#include <cuda_runtime.h>
#include <cuda_bf16.h>
#include <cstdint>
#include <cstddef>

// ---------------------------------------------------------------------------
// TaggingFNNDecoder: 2-layer LSTM tag decoder. B=32, T=256, D=1024, H=512, K=128
// Round 4: release/acquire grid barrier (no MEMBAR, central counter),
//          max-free in-loop softmax, launch order s.t. ncu slot 3 = k_loop.
// ---------------------------------------------------------------------------

#define B_  32
#define T_  256
#define D_  1024
#define H_  512
#define K_  128
#define R_  2048    // 4*H gate rows
#define KC0 640     // cell0 reduced k-dim: h1(512) + sm(128)
#define KC1 1024    // cell1 k-dim: h1(512) + h2(512)
#define G_  128     // persistent grid size (<= 148 SMs, 1 CTA/SM)

// ------------------------- device scratch ----------------------------------
__device__ float d_pre0[(size_t)T_ * R_ * B_];   // 64 MB [t][row][b]
__device__ float d_W0[(size_t)R_ * KC0];         // [row][ W_hh0 | W_ih0[:,1024:] ]
__device__ float d_W1[(size_t)R_ * KC1];         // [row][ W_ih1 | W_hh1 ]
__device__ float d_bias1[R_];
__device__ float d_h1[2 * H_ * B_];              // double buffered [j][b]
__device__ float d_h2[2 * H_ * B_];
__device__ float d_c1[H_ * B_];
__device__ float d_c2[H_ * B_];
__device__ float d_logit0[K_ * B_];              // [k][b] initial tag logits
__device__ float d_logits[(size_t)T_ * K_ * B_]; // [t][k][b] raw logits

// central barrier counter (monotonic within one launch; reset by k_zero)
__device__ unsigned g_count;

__device__ __forceinline__ float sigf(float x) {
    return 1.0f / (1.0f + __expf(-x));
}

// packed fp32x2 helpers
__device__ __forceinline__ unsigned long long pk2(float x) {
    unsigned long long r; unsigned u = __float_as_uint(x);
    asm("mov.b64 %0, {%1, %1};" : "=l"(r) : "r"(u));
    return r;
}
__device__ __forceinline__ void fma2(unsigned long long& a,
                                     unsigned long long x, unsigned long long w) {
    asm("fma.rn.f32x2 %0, %1, %2, %0;" : "+l"(a) : "l"(x), "l"(w));
}
__device__ __forceinline__ void unpk2(float& lo, float& hi, unsigned long long v) {
    unsigned l, h;
    asm("mov.b64 {%0, %1}, %2;" : "=r"(l), "=r"(h) : "l"(v));
    lo = __uint_as_float(l); hi = __uint_as_float(h);
}

// cooperative-groups-style grid barrier: syncthreads; tid0 red.release.gpu
// arrives (cumulativity publishes the whole block's prior global stores),
// then spins with ld.acquire.gpu until all G_ CTAs of this epoch arrived.
__device__ __forceinline__ void gbar(unsigned target) {
    __syncthreads();
    if (threadIdx.x == 0) {
        asm volatile("red.release.gpu.add.u32 [%0], %1;"
                     :: "l"(&g_count), "r"(1u) : "memory");
        unsigned v;
        do {
            asm volatile("ld.acquire.gpu.u32 %0, [%1];"
                         : "=r"(v) : "l"(&g_count) : "memory");
        } while ((int)(v - target) < 0);
    }
    __syncthreads();
}

// -------------------- setup: pack weights + init states ---------------------
__global__ void k_setup(const float* __restrict__ Wih0, const float* __restrict__ Whh0,
                        const float* __restrict__ Wih1, const float* __restrict__ Whh1,
                        const float* __restrict__ bih1, const float* __restrict__ bhh1,
                        const float* __restrict__ h_t,  const float* __restrict__ c_t,
                        const float* __restrict__ hid,  const float* __restrict__ W_out,
                        const float* __restrict__ b_out) {
    int row = blockIdx.x;          // 0..2047
    int tid = threadIdx.x;         // 256 threads
    // ---- weight pack ----
    const float4* s1 = (const float4*)(Whh0 + (size_t)row * H_);
    float4* dW0 = (float4*)(d_W0 + (size_t)row * KC0);
    for (int i = tid; i < H_ / 4; i += 256) dW0[i] = s1[i];
    const float4* s2 = (const float4*)(Wih0 + (size_t)row * (D_ + K_) + D_);
    for (int i = tid; i < K_ / 4; i += 256) dW0[H_ / 4 + i] = s2[i];
    float4* dW1 = (float4*)(d_W1 + (size_t)row * KC1);
    const float4* s3 = (const float4*)(Wih1 + (size_t)row * H_);
    const float4* s4 = (const float4*)(Whh1 + (size_t)row * H_);
    for (int i = tid; i < H_ / 4; i += 256) { dW1[i] = s3[i]; dW1[H_ / 4 + i] = s4[i]; }
    if (tid == 0) d_bias1[row] = bih1[row] + bhh1[row];

    // ---- state transpose (blocks 0..63) ----
    if (row < 64) {
        int idx = row * 256 + tid;                 // 0..16383 = j*32+b
        int j = idx >> 5, b = idx & 31;
        d_h1[idx] = h_t[b * H_ + j];
        d_h2[idx] = h_t[B_ * H_ + b * H_ + j];
        d_c1[idx] = c_t[b * H_ + j];
        d_c2[idx] = c_t[B_ * H_ + b * H_ + j];
    }
    // ---- initial tag logits (blocks 64..95, threads 0..127) ----
    if (row >= 64 && row < 96 && tid < 128) {
        int b = row - 64;                          // batch
        int k = tid;                               // tag
        const float* x  = hid + (size_t)b * T_ * D_;
        const float* wr = W_out + (size_t)k * H_;
        float a0 = 0.f, a1 = 0.f, a2 = 0.f, a3 = 0.f;
        for (int j = 0; j < H_; j += 4) {
            float4 w4 = *(const float4*)(wr + j);
            a0 += w4.x * x[j + 0];
            a1 += w4.y * x[j + 1];
            a2 += w4.z * x[j + 2];
            a3 += w4.w * x[j + 3];
        }
        d_logit0[k * B_ + b] = (a0 + a1) + (a2 + a3) + b_out[k];
    }
}

// reset barrier counter (small dedicated launch; also ncu slot spacer)
__global__ void k_zero() {
    if (threadIdx.x == 0) g_count = 0;
}

// -------------- pre-projection SGEMM (FFMA2): C[m][n], m = b*256+t -----------
__global__ void __launch_bounds__(256) k_pre(const float* __restrict__ A,
                                             const float* __restrict__ W,
                                             const float* __restrict__ bih,
                                             const float* __restrict__ bhh) {
    __shared__ float As[8][132];
    __shared__ float Bs[8][132];
    int tid = threadIdx.x;
    int m0 = blockIdx.y * 128;
    int n0 = blockIdx.x * 128;
    int lr = tid >> 1;
    int lc = (tid & 1) * 4;
    int ty = tid >> 4;
    int tx = tid & 15;

    unsigned long long acc2[8][4];
#pragma unroll
    for (int i = 0; i < 8; i++)
#pragma unroll
        for (int j = 0; j < 4; j++) acc2[i][j] = 0ull;

    for (int kt = 0; kt < D_; kt += 8) {
        float4 a = *(const float4*)&A[(size_t)(m0 + lr) * D_ + kt + lc];
        As[lc + 0][lr] = a.x; As[lc + 1][lr] = a.y;
        As[lc + 2][lr] = a.z; As[lc + 3][lr] = a.w;
        float4 b = *(const float4*)&W[(size_t)(n0 + lr) * (D_ + K_) + kt + lc];
        Bs[lc + 0][lr] = b.x; Bs[lc + 1][lr] = b.y;
        Bs[lc + 2][lr] = b.z; Bs[lc + 3][lr] = b.w;
        __syncthreads();
#pragma unroll
        for (int k = 0; k < 8; k++) {
            float4 raA = *(const float4*)&As[k][ty * 4];
            float4 raB = *(const float4*)&As[k][64 + ty * 4];
            ulonglong2 rbA = *(const ulonglong2*)&Bs[k][tx * 4];
            ulonglong2 rbB = *(const ulonglong2*)&Bs[k][64 + tx * 4];
            float ra[8] = {raA.x, raA.y, raA.z, raA.w, raB.x, raB.y, raB.z, raB.w};
#pragma unroll
            for (int i = 0; i < 8; i++) {
                unsigned long long ax = pk2(ra[i]);
                fma2(acc2[i][0], ax, rbA.x);
                fma2(acc2[i][1], ax, rbA.y);
                fma2(acc2[i][2], ax, rbB.x);
                fma2(acc2[i][3], ax, rbB.y);
            }
        }
        __syncthreads();
    }

#pragma unroll
    for (int i = 0; i < 8; i++) {
        int m = m0 + ((i < 4) ? (ty * 4 + i) : (64 + ty * 4 + i - 4));
        int tt = m & 255;
        int bb = m >> 8;
#pragma unroll
        for (int j2 = 0; j2 < 4; j2++) {
            float lo, hi;
            unpk2(lo, hi, acc2[i][j2]);
            int nb = (j2 < 2) ? (n0 + tx * 4 + j2 * 2)
                              : (n0 + 64 + tx * 4 + (j2 - 2) * 2);
            d_pre0[((size_t)tt * R_ + nb + 0) * B_ + bb] = lo + bih[nb] + bhh[nb];
            d_pre0[((size_t)tt * R_ + nb + 1) * B_ + bb] = hi + bih[nb + 1] + bhh[nb + 1];
        }
    }
}

// ------------------------- persistent recurrence -----------------------------
// 128 CTAs x 512 threads (16 warps). CTA c owns hidden units u = c*4..c*4+3 for
// both LSTM layers (16 gate rows each, local row r = g*4+ul) and tag row c.
// Weights k-major in SMEM: w0s[k*16+r], w1s[k*16+r]. lane = batch everywhere.
__global__ void __launch_bounds__(512, 1) k_loop(const float* __restrict__ W_out,
                                                 const float* __restrict__ b_out) {
    extern __shared__ float smem[];
    float* w0s     = smem;                    // 640*16  = 10240
    float* w1s     = w0s + KC0 * 16;          // 1024*16 = 16384
    float* wout    = w1s + KC1 * 16;          // 512
    float* bias1s  = wout + 512;              // 16 (padded to 32)
    float* smx     = bias1s + 32;             // 128*33 = 4224
    float* partial = smx + 128 * 33;          // 16*16*32 = 8192
    float* pout    = partial + 8192;          // 16*32 = 512

    const int c    = blockIdx.x;
    const int tid  = threadIdx.x;
    const int lane = tid & 31;
    const int w    = tid >> 5;                // 16 warps

    // ---- stage weights into SMEM (once) ----
#pragma unroll
    for (int r = 0; r < 16; r++) {
        int grow = (r >> 2) * H_ + c * 4 + (r & 3);
        const float* src0 = d_W0 + (size_t)grow * KC0;
        for (int k = tid; k < KC0; k += 512) w0s[k * 16 + r] = src0[k];
        const float* src1 = d_W1 + (size_t)grow * KC1;
        for (int k = tid; k < KC1; k += 512) w1s[k * 16 + r] = src1[k];
        if (tid == 0) bias1s[r] = d_bias1[grow];
    }
    for (int j = tid; j < H_; j += 512) wout[j] = W_out[(size_t)c * H_ + j];
    __syncthreads();

    // ---- per-thread cell state (tid<128): b = tid&31, ul = tid>>5 ----
    float c1_reg = 0.f, c2_reg = 0.f;
    int b = tid & 31, ul = tid >> 5;          // ul 0..15; only ul<4 used
    int u = c * 4 + (ul & 3);
    if (tid < 128) {
        c1_reg = d_c1[u * 32 + b];
        c2_reg = d_c2[u * 32 + b];
    }
    float bout_c = b_out[c];

    unsigned tgt = G_;

    for (int t = 0; t < T_; t++) {
        const int old = t & 1, nw = old ^ 1;
        const float* __restrict__ h1old = d_h1 + old * (H_ * B_);
        float*       __restrict__ h1new = d_h1 + nw  * (H_ * B_);
        const float* __restrict__ h2old = d_h2 + old * (H_ * B_);
        float*       __restrict__ h2new = d_h2 + nw  * (H_ * B_);

        // prefetch pre0 gate terms (hidden under softmax + cell0 dot)
        float pre[4];
        if (tid < 128) {
#pragma unroll
            for (int g = 0; g < 4; g++)
                pre[g] = __ldcg(&d_pre0[((size_t)t * R_ + g * H_ + u) * B_ + b]);
        }

        // ---- stage prev logits coalesced, then softmax into smx[k*33+b] ----
        {
            const float* lg = (t == 0) ? d_logit0
                                       : d_logits + (size_t)(t - 1) * K_ * B_;
#pragma unroll
            for (int kk = 0; kk < 8; kk++) {
                int k = w * 8 + kk;
                smx[k * 33 + lane] = __ldcg(lg + k * 32 + lane);
            }
        }
        __syncthreads();
        {
            // warp w normalizes batches 2w, 2w+1; lanes index tags.
            // logits are O(1): exp without max subtraction is safe here.
#pragma unroll
            for (int bb = 0; bb < 2; bb++) {
                int bq = w * 2 + bb;
                float v[4];
                float s = 0.f;
#pragma unroll
                for (int i = 0; i < 4; i++) {
                    v[i] = __expf(smx[(lane + 32 * i) * 33 + bq]);
                    s += v[i];
                }
#pragma unroll
                for (int o = 16; o > 0; o >>= 1) s += __shfl_xor_sync(~0u, s, o);
                float inv = 1.0f / s;
#pragma unroll
                for (int i = 0; i < 4; i++) smx[(lane + 32 * i) * 33 + bq] = v[i] * inv;
            }
        }
        __syncthreads();

        // =================== cell0 dot: 16 rows, k-sliced over 16 warps ======
        {
            unsigned long long acc[8];
#pragma unroll
            for (int p = 0; p < 8; p++) acc[p] = 0ull;

            int kb = w * 32;
#pragma unroll 16
            for (int kk = 0; kk < 32; kk++) {
                int k = kb + kk;
                unsigned long long xx = pk2(__ldcg(h1old + k * 32 + lane));
                const ulonglong2* q = (const ulonglong2*)(w0s + k * 16);
                ulonglong2 q0 = q[0], q1 = q[1], q2 = q[2], q3 = q[3];
                fma2(acc[0], xx, q0.x); fma2(acc[1], xx, q0.y);
                fma2(acc[2], xx, q1.x); fma2(acc[3], xx, q1.y);
                fma2(acc[4], xx, q2.x); fma2(acc[5], xx, q2.y);
                fma2(acc[6], xx, q3.x); fma2(acc[7], xx, q3.y);
            }
            int kb2 = w * 8;
#pragma unroll
            for (int kk = 0; kk < 8; kk++) {
                int k = H_ + kb2 + kk;
                unsigned long long xx = pk2(smx[(kb2 + kk) * 33 + lane]);
                const ulonglong2* q = (const ulonglong2*)(w0s + k * 16);
                ulonglong2 q0 = q[0], q1 = q[1], q2 = q[2], q3 = q[3];
                fma2(acc[0], xx, q0.x); fma2(acc[1], xx, q0.y);
                fma2(acc[2], xx, q1.x); fma2(acc[3], xx, q1.y);
                fma2(acc[4], xx, q2.x); fma2(acc[5], xx, q2.y);
                fma2(acc[6], xx, q3.x); fma2(acc[7], xx, q3.y);
            }
#pragma unroll
            for (int p = 0; p < 8; p++) {
                float lo, hi; unpk2(lo, hi, acc[p]);
                partial[(w * 16 + 2 * p + 0) * 32 + lane] = lo;
                partial[(w * 16 + 2 * p + 1) * 32 + lane] = hi;
            }
        }
        __syncthreads();

        if (tid < 128) {
            float gate[4];
#pragma unroll
            for (int g = 0; g < 4; g++) {
                int r = g * 4 + ul;
                float s = pre[g];
#pragma unroll
                for (int w2 = 0; w2 < 16; w2++) s += partial[(w2 * 16 + r) * 32 + b];
                gate[g] = s;
            }
            float iv = sigf(gate[0]);
            float fv = sigf(gate[1]);
            float gv = tanhf(gate[2]);
            float ov = sigf(gate[3]);
            c1_reg = fv * c1_reg + iv * gv;
            h1new[u * 32 + b] = ov * tanhf(c1_reg);
        }
        gbar(tgt); tgt += G_;

        // =================== cell1 dot: 16 rows, k = [h1new; h2old] ==========
        {
            unsigned long long acc[8];
#pragma unroll
            for (int p = 0; p < 8; p++) acc[p] = 0ull;

            // warps 0..7 -> h1new slice, warps 8..15 -> h2old slice
            const float* __restrict__ xsrc =
                (w < 8) ? (h1new + (w * 64) * 32) : (h2old + ((w - 8) * 64) * 32);
            const float* wbase = w1s + (w * 64) * 16;
#pragma unroll 16
            for (int kk = 0; kk < 64; kk++) {
                unsigned long long xx = pk2(__ldcg(xsrc + kk * 32 + lane));
                const ulonglong2* q = (const ulonglong2*)(wbase + kk * 16);
                ulonglong2 q0 = q[0], q1 = q[1], q2 = q[2], q3 = q[3];
                fma2(acc[0], xx, q0.x); fma2(acc[1], xx, q0.y);
                fma2(acc[2], xx, q1.x); fma2(acc[3], xx, q1.y);
                fma2(acc[4], xx, q2.x); fma2(acc[5], xx, q2.y);
                fma2(acc[6], xx, q3.x); fma2(acc[7], xx, q3.y);
            }
#pragma unroll
            for (int p = 0; p < 8; p++) {
                float lo, hi; unpk2(lo, hi, acc[p]);
                partial[(w * 16 + 2 * p + 0) * 32 + lane] = lo;
                partial[(w * 16 + 2 * p + 1) * 32 + lane] = hi;
            }
        }
        __syncthreads();

        if (tid < 128) {
            float gate[4];
#pragma unroll
            for (int g = 0; g < 4; g++) {
                int r = g * 4 + ul;
                float s = bias1s[r];
#pragma unroll
                for (int w2 = 0; w2 < 16; w2++) s += partial[(w2 * 16 + r) * 32 + b];
                gate[g] = s;
            }
            float iv = sigf(gate[0]);
            float fv = sigf(gate[1]);
            float gv = tanhf(gate[2]);
            float ov = sigf(gate[3]);
            c2_reg = fv * c2_reg + iv * gv;
            h2new[u * 32 + b] = ov * tanhf(c2_reg);
        }
        gbar(tgt); tgt += G_;

        // =================== out: tag row c, j-sliced over 16 warps ==========
        {
            float a = 0.f;
            int jb = w * 32;
#pragma unroll 16
            for (int jj = 0; jj < 32; jj++) {
                int j = jb + jj;
                a += wout[j] * __ldcg(h2new + j * 32 + lane);
            }
            pout[w * 32 + lane] = a;
        }
        __syncthreads();
        if (tid < 32) {
            float s = bout_c;
#pragma unroll
            for (int w2 = 0; w2 < 16; w2++) s += pout[w2 * 32 + tid];
            d_logits[((size_t)t * K_ + c) * 32 + tid] = s;
        }
        gbar(tgt); tgt += G_;
    }
}

// --------------------------- final masked softmax ----------------------------
__global__ void __launch_bounds__(256) k_final(const float* __restrict__ mask,
                                               float* __restrict__ out) {
    int tid = threadIdx.x, lane = tid & 31, w = tid >> 5;
    int gidx = blockIdx.x * 8 + w;             // 0..8191
    int b = gidx >> 8, t = gidx & 255;
    float pen = (1.0f - mask[b * T_ + t]) * -1e32f;
    float v[4];
#pragma unroll
    for (int i = 0; i < 4; i++)
        v[i] = d_logits[((size_t)t * K_ + lane + 32 * i) * B_ + b] + pen;
    float mx = fmaxf(fmaxf(v[0], v[1]), fmaxf(v[2], v[3]));
#pragma unroll
    for (int o = 16; o > 0; o >>= 1) mx = fmaxf(mx, __shfl_xor_sync(~0u, mx, o));
    float s = 0.f;
#pragma unroll
    for (int i = 0; i < 4; i++) { v[i] = __expf(v[i] - mx); s += v[i]; }
#pragma unroll
    for (int o = 16; o > 0; o >>= 1) s += __shfl_xor_sync(~0u, s, o);
    float inv = 1.0f / s;
#pragma unroll
    for (int i = 0; i < 4; i++)
        out[((size_t)b * T_ + t) * K_ + lane + 32 * i] = v[i] * inv;
}

// ----------------------------------------------------------------------------
extern "C" void kernel_launch(void* const* d_in, const int* in_sizes, int n_in,
                              void* d_out, int out_size) {
    const float* hiddens = (const float*)d_in[0];
    const float* h_t     = (const float*)d_in[1];
    const float* c_t     = (const float*)d_in[2];
    const float* mask    = (const float*)d_in[3];
    const float* W_out   = (const float*)d_in[4];
    const float* b_out   = (const float*)d_in[5];
    const float* W_ih0   = (const float*)d_in[6];
    const float* W_hh0   = (const float*)d_in[7];
    const float* b_ih0   = (const float*)d_in[8];
    const float* b_hh0   = (const float*)d_in[9];
    const float* W_ih1   = (const float*)d_in[10];
    const float* W_hh1   = (const float*)d_in[11];
    const float* b_ih1   = (const float*)d_in[12];
    const float* b_hh1   = (const float*)d_in[13];
    float* out = (float*)d_out;

    // SMEM: w0s 10240 + w1s 16384 + wout 512 + bias1s 32 + smx 4224
    //       + partial 8192 + pout 512 = 40096 floats = 160384 bytes
    const int SMEM_LOOP = 40096 * 4;
    cudaFuncSetAttribute(k_loop, cudaFuncAttributeMaxDynamicSharedMemorySize, SMEM_LOOP);

    // launch order: slot 3 (the one ncu captures) = k_loop
    k_setup<<<R_, 256>>>(W_ih0, W_hh0, W_ih1, W_hh1, b_ih1, b_hh1,
                         h_t, c_t, hiddens, W_out, b_out);
    k_pre<<<dim3(16, 64), 256>>>(hiddens, W_ih0, b_ih0, b_hh0);
    k_zero<<<1, 32>>>();
    k_loop<<<G_, 512, SMEM_LOOP>>>(W_out, b_out);
    k_final<<<1024, 256>>>(mask, out);
}

// round 6
// speedup vs baseline: 3.6623x; 1.0848x over previous
#include <cuda_runtime.h>
#include <cuda_bf16.h>
#include <cstdint>
#include <cstddef>

// ---------------------------------------------------------------------------
// TaggingFNNDecoder: 2-layer LSTM tag decoder. B=32, T=256, D=1024, H=512, K=128
// Round 5: 2 grid barriers/step (atomic logit scatter), deferred-normalization
//          softmax folded into cell0 dot, k_pre K-tile 16.
// ---------------------------------------------------------------------------

#define B_  32
#define T_  256
#define D_  1024
#define H_  512
#define K_  128
#define R_  2048    // 4*H gate rows
#define KC0 640     // cell0 reduced k-dim: h1(512) + e(128)
#define KC1 1024    // cell1 k-dim: h1(512) + h2(512)
#define G_  128     // persistent grid size (<= 148 SMs, 1 CTA/SM)

// ------------------------- device scratch ----------------------------------
__device__ float d_pre0[(size_t)T_ * R_ * B_];   // 64 MB [t][row][b]
__device__ float d_W0[(size_t)R_ * KC0];         // [row][ W_hh0 | W_ih0[:,1024:] ]
__device__ float d_W1[(size_t)R_ * KC1];         // [row][ W_ih1 | W_hh1 ]
__device__ float d_bias1[R_];
__device__ float d_h1[2 * H_ * B_];              // double buffered [j][b]
__device__ float d_h2[2 * H_ * B_];
__device__ float d_c1[H_ * B_];
__device__ float d_c2[H_ * B_];
__device__ float d_logit0[K_ * B_];              // [k][b] initial tag logits
__device__ float d_logits[(size_t)T_ * K_ * B_]; // [t][k][b] raw logits

// central barrier counter (monotonic within one launch; reset by k_zero)
__device__ unsigned g_count;

__device__ __forceinline__ float sigf(float x) {
    return 1.0f / (1.0f + __expf(-x));
}

// packed fp32x2 helpers
__device__ __forceinline__ unsigned long long pk2(float x) {
    unsigned long long r; unsigned u = __float_as_uint(x);
    asm("mov.b64 %0, {%1, %1};" : "=l"(r) : "r"(u));
    return r;
}
__device__ __forceinline__ void fma2(unsigned long long& a,
                                     unsigned long long x, unsigned long long w) {
    asm("fma.rn.f32x2 %0, %1, %2, %0;" : "+l"(a) : "l"(x), "l"(w));
}
__device__ __forceinline__ void unpk2(float& lo, float& hi, unsigned long long v) {
    unsigned l, h;
    asm("mov.b64 {%0, %1}, %2;" : "=r"(l), "=r"(h) : "l"(v));
    lo = __uint_as_float(l); hi = __uint_as_float(h);
}

// cooperative-groups-style grid barrier: syncthreads; tid0 red.release.gpu
// arrives (cumulativity publishes the whole block's prior global stores &
// reductions), then spins with ld.acquire.gpu until all G_ CTAs arrived.
__device__ __forceinline__ void gbar(unsigned target) {
    __syncthreads();
    if (threadIdx.x == 0) {
        asm volatile("red.release.gpu.add.u32 [%0], %1;"
                     :: "l"(&g_count), "r"(1u) : "memory");
        unsigned v;
        do {
            asm volatile("ld.acquire.gpu.u32 %0, [%1];"
                         : "=r"(v) : "l"(&g_count) : "memory");
        } while ((int)(v - target) < 0);
    }
    __syncthreads();
}

// -------------------- setup: pack weights + init states ---------------------
__global__ void k_setup(const float* __restrict__ Wih0, const float* __restrict__ Whh0,
                        const float* __restrict__ Wih1, const float* __restrict__ Whh1,
                        const float* __restrict__ bih1, const float* __restrict__ bhh1,
                        const float* __restrict__ h_t,  const float* __restrict__ c_t,
                        const float* __restrict__ hid,  const float* __restrict__ W_out,
                        const float* __restrict__ b_out) {
    int row = blockIdx.x;          // 0..2047
    int tid = threadIdx.x;         // 256 threads
    // ---- weight pack ----
    const float4* s1 = (const float4*)(Whh0 + (size_t)row * H_);
    float4* dW0 = (float4*)(d_W0 + (size_t)row * KC0);
    for (int i = tid; i < H_ / 4; i += 256) dW0[i] = s1[i];
    const float4* s2 = (const float4*)(Wih0 + (size_t)row * (D_ + K_) + D_);
    for (int i = tid; i < K_ / 4; i += 256) dW0[H_ / 4 + i] = s2[i];
    float4* dW1 = (float4*)(d_W1 + (size_t)row * KC1);
    const float4* s3 = (const float4*)(Wih1 + (size_t)row * H_);
    const float4* s4 = (const float4*)(Whh1 + (size_t)row * H_);
    for (int i = tid; i < H_ / 4; i += 256) { dW1[i] = s3[i]; dW1[H_ / 4 + i] = s4[i]; }
    if (tid == 0) d_bias1[row] = bih1[row] + bhh1[row];

    // ---- logits prefill with output bias (blocks 0..255 <-> t) ----
    if (row < 256) {
        float* dst = d_logits + (size_t)row * K_ * B_;
        for (int i = tid; i < K_ * B_; i += 256) dst[i] = b_out[i >> 5];
    }
    // ---- state transpose (blocks 0..63) ----
    if (row < 64) {
        int idx = row * 256 + tid;                 // 0..16383 = j*32+b
        int j = idx >> 5, b = idx & 31;
        d_h1[idx] = h_t[b * H_ + j];
        d_h2[idx] = h_t[B_ * H_ + b * H_ + j];
        d_c1[idx] = c_t[b * H_ + j];
        d_c2[idx] = c_t[B_ * H_ + b * H_ + j];
    }
    // ---- initial tag logits (blocks 64..95, threads 0..127) ----
    if (row >= 64 && row < 96 && tid < 128) {
        int b = row - 64;                          // batch
        int k = tid;                               // tag
        const float* x  = hid + (size_t)b * T_ * D_;
        const float* wr = W_out + (size_t)k * H_;
        float a0 = 0.f, a1 = 0.f, a2 = 0.f, a3 = 0.f;
        for (int j = 0; j < H_; j += 4) {
            float4 w4 = *(const float4*)(wr + j);
            a0 += w4.x * x[j + 0];
            a1 += w4.y * x[j + 1];
            a2 += w4.z * x[j + 2];
            a3 += w4.w * x[j + 3];
        }
        d_logit0[k * B_ + b] = (a0 + a1) + (a2 + a3) + b_out[k];
    }
}

// reset barrier counter
__global__ void k_zero() {
    if (threadIdx.x == 0) g_count = 0;
}

// -------------- pre-projection SGEMM (FFMA2, K-tile 16) ----------------------
__global__ void __launch_bounds__(256) k_pre(const float* __restrict__ A,
                                             const float* __restrict__ W,
                                             const float* __restrict__ bih,
                                             const float* __restrict__ bhh) {
    __shared__ float As[16][132];
    __shared__ float Bs[16][132];
    int tid = threadIdx.x;
    int m0 = blockIdx.y * 128;
    int n0 = blockIdx.x * 128;
    int lr = tid >> 1;
    int lc = (tid & 1) * 4;
    int ty = tid >> 4;
    int tx = tid & 15;

    unsigned long long acc2[8][4];
#pragma unroll
    for (int i = 0; i < 8; i++)
#pragma unroll
        for (int j = 0; j < 4; j++) acc2[i][j] = 0ull;

    for (int kt = 0; kt < D_; kt += 16) {
        float4 a0 = *(const float4*)&A[(size_t)(m0 + lr) * D_ + kt + lc];
        float4 a1 = *(const float4*)&A[(size_t)(m0 + lr) * D_ + kt + 8 + lc];
        float4 b0 = *(const float4*)&W[(size_t)(n0 + lr) * (D_ + K_) + kt + lc];
        float4 b1 = *(const float4*)&W[(size_t)(n0 + lr) * (D_ + K_) + kt + 8 + lc];
        As[lc + 0][lr] = a0.x; As[lc + 1][lr] = a0.y;
        As[lc + 2][lr] = a0.z; As[lc + 3][lr] = a0.w;
        As[8 + lc + 0][lr] = a1.x; As[8 + lc + 1][lr] = a1.y;
        As[8 + lc + 2][lr] = a1.z; As[8 + lc + 3][lr] = a1.w;
        Bs[lc + 0][lr] = b0.x; Bs[lc + 1][lr] = b0.y;
        Bs[lc + 2][lr] = b0.z; Bs[lc + 3][lr] = b0.w;
        Bs[8 + lc + 0][lr] = b1.x; Bs[8 + lc + 1][lr] = b1.y;
        Bs[8 + lc + 2][lr] = b1.z; Bs[8 + lc + 3][lr] = b1.w;
        __syncthreads();
#pragma unroll 16
        for (int k = 0; k < 16; k++) {
            float4 raA = *(const float4*)&As[k][ty * 4];
            float4 raB = *(const float4*)&As[k][64 + ty * 4];
            ulonglong2 rbA = *(const ulonglong2*)&Bs[k][tx * 4];
            ulonglong2 rbB = *(const ulonglong2*)&Bs[k][64 + tx * 4];
            float ra[8] = {raA.x, raA.y, raA.z, raA.w, raB.x, raB.y, raB.z, raB.w};
#pragma unroll
            for (int i = 0; i < 8; i++) {
                unsigned long long ax = pk2(ra[i]);
                fma2(acc2[i][0], ax, rbA.x);
                fma2(acc2[i][1], ax, rbA.y);
                fma2(acc2[i][2], ax, rbB.x);
                fma2(acc2[i][3], ax, rbB.y);
            }
        }
        __syncthreads();
    }

#pragma unroll
    for (int i = 0; i < 8; i++) {
        int m = m0 + ((i < 4) ? (ty * 4 + i) : (64 + ty * 4 + i - 4));
        int tt = m & 255;
        int bb = m >> 8;
#pragma unroll
        for (int j2 = 0; j2 < 4; j2++) {
            float lo, hi;
            unpk2(lo, hi, acc2[i][j2]);
            int nb = (j2 < 2) ? (n0 + tx * 4 + j2 * 2)
                              : (n0 + 64 + tx * 4 + (j2 - 2) * 2);
            d_pre0[((size_t)tt * R_ + nb + 0) * B_ + bb] = lo + bih[nb] + bhh[nb];
            d_pre0[((size_t)tt * R_ + nb + 1) * B_ + bb] = hi + bih[nb + 1] + bhh[nb + 1];
        }
    }
}

// ------------------------- persistent recurrence -----------------------------
// 128 CTAs x 512 threads (16 warps). CTA c owns hidden units u = c*4..c*4+3 for
// both LSTM layers (16 gate rows each, local row r = g*4+ul).
// Two grid barriers per step:
//   phase A: cell0 (exp/Z folded into dot)  -> bar
//   phase B: cell1 + atomic logit scatter   -> bar
__global__ void __launch_bounds__(512, 1) k_loop(const float* __restrict__ W_out,
                                                 const float* __restrict__ b_out) {
    extern __shared__ float smem[];
    float* w0s     = smem;                    // 640*16  = 10240
    float* w1s     = w0s + KC0 * 16;          // 1024*16 = 16384
    float* woutT   = w1s + KC1 * 16;          // [ul][k] 4*128 = 512
    float* bias1s  = woutT + 512;             // 16 (padded to 32)
    float* parth   = bias1s + 32;             // 16*16*32 = 8192
    float* parte   = parth + 8192;            // 16*16*32 = 8192
    float* zps     = parte + 8192;            // 16*32 = 512
    float* h2s     = zps + 512;               // 4*32 = 128

    const int c    = blockIdx.x;
    const int tid  = threadIdx.x;
    const int lane = tid & 31;
    const int w    = tid >> 5;                // 16 warps

    // ---- stage weights into SMEM (once) ----
#pragma unroll
    for (int r = 0; r < 16; r++) {
        int grow = (r >> 2) * H_ + c * 4 + (r & 3);
        const float* src0 = d_W0 + (size_t)grow * KC0;
        for (int k = tid; k < KC0; k += 512) w0s[k * 16 + r] = src0[k];
        const float* src1 = d_W1 + (size_t)grow * KC1;
        for (int k = tid; k < KC1; k += 512) w1s[k * 16 + r] = src1[k];
        if (tid == 0) bias1s[r] = d_bias1[grow];
    }
    // W_out columns for this CTA's 4 units, transposed: woutT[ul*128 + k]
    for (int i = tid; i < 512; i += 512) {
        int ul = i >> 7, k = i & 127;
        woutT[i] = W_out[(size_t)k * H_ + c * 4 + ul];
    }
    __syncthreads();

    // ---- per-thread cell state (tid<128): b = tid&31, ul = tid>>5 ----
    float c1_reg = 0.f, c2_reg = 0.f;
    int b = tid & 31, ul = tid >> 5;          // ul 0..15; only ul<4 used
    int u = c * 4 + (ul & 3);
    if (tid < 128) {
        c1_reg = d_c1[u * 32 + b];
        c2_reg = d_c2[u * 32 + b];
    }

    unsigned tgt = G_;

    for (int t = 0; t < T_; t++) {
        const int old = t & 1, nw = old ^ 1;
        const float* __restrict__ h1old = d_h1 + old * (H_ * B_);
        float*       __restrict__ h1new = d_h1 + nw  * (H_ * B_);
        const float* __restrict__ h2old = d_h2 + old * (H_ * B_);
        float*       __restrict__ h2new = d_h2 + nw  * (H_ * B_);

        // prefetch pre0 gate terms (consumed in gate phase A)
        float pre[4];
        if (tid < 128) {
#pragma unroll
            for (int g = 0; g < 4; g++)
                pre[g] = __ldcg(&d_pre0[((size_t)t * R_ + g * H_ + u) * B_ + b]);
        }

        // ============ phase A: cell0 dot (h-part + e-part with Z) ============
        {
            unsigned long long acch[8], acce[8];
#pragma unroll
            for (int p = 0; p < 8; p++) { acch[p] = 0ull; acce[p] = 0ull; }

            int kb = w * 32;
#pragma unroll 16
            for (int kk = 0; kk < 32; kk++) {
                int k = kb + kk;
                unsigned long long xx = pk2(__ldcg(h1old + k * 32 + lane));
                const ulonglong2* q = (const ulonglong2*)(w0s + k * 16);
                ulonglong2 q0 = q[0], q1 = q[1], q2 = q[2], q3 = q[3];
                fma2(acch[0], xx, q0.x); fma2(acch[1], xx, q0.y);
                fma2(acch[2], xx, q1.x); fma2(acch[3], xx, q1.y);
                fma2(acch[4], xx, q2.x); fma2(acch[5], xx, q2.y);
                fma2(acch[6], xx, q3.x); fma2(acch[7], xx, q3.y);
            }
            // e-part: 8 tags per warp; exp on the fly, accumulate Z
            const float* lg = (t == 0) ? d_logit0
                                       : d_logits + (size_t)(t - 1) * K_ * B_;
            float zp = 0.f;
            int ke0 = w * 8;
#pragma unroll
            for (int kk = 0; kk < 8; kk++) {
                float ev = __expf(__ldcg(lg + (ke0 + kk) * 32 + lane));
                zp += ev;
                unsigned long long xx = pk2(ev);
                const ulonglong2* q = (const ulonglong2*)(w0s + (H_ + ke0 + kk) * 16);
                ulonglong2 q0 = q[0], q1 = q[1], q2 = q[2], q3 = q[3];
                fma2(acce[0], xx, q0.x); fma2(acce[1], xx, q0.y);
                fma2(acce[2], xx, q1.x); fma2(acce[3], xx, q1.y);
                fma2(acce[4], xx, q2.x); fma2(acce[5], xx, q2.y);
                fma2(acce[6], xx, q3.x); fma2(acce[7], xx, q3.y);
            }
            zps[w * 32 + lane] = zp;
#pragma unroll
            for (int p = 0; p < 8; p++) {
                float lo, hi;
                unpk2(lo, hi, acch[p]);
                parth[(w * 16 + 2 * p + 0) * 32 + lane] = lo;
                parth[(w * 16 + 2 * p + 1) * 32 + lane] = hi;
                unpk2(lo, hi, acce[p]);
                parte[(w * 16 + 2 * p + 0) * 32 + lane] = lo;
                parte[(w * 16 + 2 * p + 1) * 32 + lane] = hi;
            }
        }
        __syncthreads();

        if (tid < 128) {
            float Z = 0.f;
#pragma unroll
            for (int w2 = 0; w2 < 16; w2++) Z += zps[w2 * 32 + b];
            float invZ = 1.0f / Z;
            float gate[4];
#pragma unroll
            for (int g = 0; g < 4; g++) {
                int r = g * 4 + ul;
                float sh = pre[g], se = 0.f;
#pragma unroll
                for (int w2 = 0; w2 < 16; w2++) {
                    sh += parth[(w2 * 16 + r) * 32 + b];
                    se += parte[(w2 * 16 + r) * 32 + b];
                }
                gate[g] = sh + se * invZ;
            }
            float iv = sigf(gate[0]);
            float fv = sigf(gate[1]);
            float gv = tanhf(gate[2]);
            float ov = sigf(gate[3]);
            c1_reg = fv * c1_reg + iv * gv;
            h1new[u * 32 + b] = ov * tanhf(c1_reg);
        }
        gbar(tgt); tgt += G_;

        // ============ phase B: cell1 dot + gate + logit scatter ==============
        {
            unsigned long long acc[8];
#pragma unroll
            for (int p = 0; p < 8; p++) acc[p] = 0ull;

            // warps 0..7 -> h1new slice, warps 8..15 -> h2old slice
            const float* __restrict__ xsrc =
                (w < 8) ? (h1new + (w * 64) * 32) : (h2old + ((w - 8) * 64) * 32);
            const float* wbase = w1s + (w * 64) * 16;
#pragma unroll 16
            for (int kk = 0; kk < 64; kk++) {
                unsigned long long xx = pk2(__ldcg(xsrc + kk * 32 + lane));
                const ulonglong2* q = (const ulonglong2*)(wbase + kk * 16);
                ulonglong2 q0 = q[0], q1 = q[1], q2 = q[2], q3 = q[3];
                fma2(acc[0], xx, q0.x); fma2(acc[1], xx, q0.y);
                fma2(acc[2], xx, q1.x); fma2(acc[3], xx, q1.y);
                fma2(acc[4], xx, q2.x); fma2(acc[5], xx, q2.y);
                fma2(acc[6], xx, q3.x); fma2(acc[7], xx, q3.y);
            }
#pragma unroll
            for (int p = 0; p < 8; p++) {
                float lo, hi; unpk2(lo, hi, acc[p]);
                parth[(w * 16 + 2 * p + 0) * 32 + lane] = lo;
                parth[(w * 16 + 2 * p + 1) * 32 + lane] = hi;
            }
        }
        __syncthreads();

        if (tid < 128) {
            float gate[4];
#pragma unroll
            for (int g = 0; g < 4; g++) {
                int r = g * 4 + ul;
                float s = bias1s[r];
#pragma unroll
                for (int w2 = 0; w2 < 16; w2++) s += parth[(w2 * 16 + r) * 32 + b];
                gate[g] = s;
            }
            float iv = sigf(gate[0]);
            float fv = sigf(gate[1]);
            float gv = tanhf(gate[2]);
            float ov = sigf(gate[3]);
            c2_reg = fv * c2_reg + iv * gv;
            float h2v = ov * tanhf(c2_reg);
            h2new[u * 32 + b] = h2v;
            h2s[(ul & 3) * 32 + b] = h2v;
        }
        __syncthreads();

        // scatter: warp w owns tags k = w*8 .. w*8+7; lane = batch
        {
            float h0 = h2s[lane];
            float h1v = h2s[32 + lane];
            float h2q = h2s[64 + lane];
            float h3 = h2s[96 + lane];
            float* dstl = d_logits + ((size_t)t * K_) * B_;
            int k0 = w * 8;
#pragma unroll
            for (int kk = 0; kk < 8; kk++) {
                int kq = k0 + kk;
                float v = woutT[kq] * h0 + woutT[128 + kq] * h1v
                        + woutT[256 + kq] * h2q + woutT[384 + kq] * h3;
                atomicAdd(dstl + kq * B_ + lane, v);
            }
        }
        gbar(tgt); tgt += G_;
    }
}

// --------------------------- final masked softmax ----------------------------
__global__ void __launch_bounds__(256) k_final(const float* __restrict__ mask,
                                               float* __restrict__ out) {
    int tid = threadIdx.x, lane = tid & 31, w = tid >> 5;
    int gidx = blockIdx.x * 8 + w;             // 0..8191
    int b = gidx >> 8, t = gidx & 255;
    float pen = (1.0f - mask[b * T_ + t]) * -1e32f;
    float v[4];
#pragma unroll
    for (int i = 0; i < 4; i++)
        v[i] = d_logits[((size_t)t * K_ + lane + 32 * i) * B_ + b] + pen;
    float mx = fmaxf(fmaxf(v[0], v[1]), fmaxf(v[2], v[3]));
#pragma unroll
    for (int o = 16; o > 0; o >>= 1) mx = fmaxf(mx, __shfl_xor_sync(~0u, mx, o));
    float s = 0.f;
#pragma unroll
    for (int i = 0; i < 4; i++) { v[i] = __expf(v[i] - mx); s += v[i]; }
#pragma unroll
    for (int o = 16; o > 0; o >>= 1) s += __shfl_xor_sync(~0u, s, o);
    float inv = 1.0f / s;
#pragma unroll
    for (int i = 0; i < 4; i++)
        out[((size_t)b * T_ + t) * K_ + lane + 32 * i] = v[i] * inv;
}

// ----------------------------------------------------------------------------
extern "C" void kernel_launch(void* const* d_in, const int* in_sizes, int n_in,
                              void* d_out, int out_size) {
    const float* hiddens = (const float*)d_in[0];
    const float* h_t     = (const float*)d_in[1];
    const float* c_t     = (const float*)d_in[2];
    const float* mask    = (const float*)d_in[3];
    const float* W_out   = (const float*)d_in[4];
    const float* b_out   = (const float*)d_in[5];
    const float* W_ih0   = (const float*)d_in[6];
    const float* W_hh0   = (const float*)d_in[7];
    const float* b_ih0   = (const float*)d_in[8];
    const float* b_hh0   = (const float*)d_in[9];
    const float* W_ih1   = (const float*)d_in[10];
    const float* W_hh1   = (const float*)d_in[11];
    const float* b_ih1   = (const float*)d_in[12];
    const float* b_hh1   = (const float*)d_in[13];
    float* out = (float*)d_out;

    // SMEM floats: w0s 10240 + w1s 16384 + woutT 512 + bias1s 32
    //            + parth 8192 + parte 8192 + zps 512 + h2s 128 = 44192
    const int SMEM_LOOP = 44192 * 4;   // 176768 bytes
    cudaFuncSetAttribute(k_loop, cudaFuncAttributeMaxDynamicSharedMemorySize, SMEM_LOOP);

    // launch order: slot 3 (the one ncu captures) = k_loop
    k_setup<<<R_, 256>>>(W_ih0, W_hh0, W_ih1, W_hh1, b_ih1, b_hh1,
                         h_t, c_t, hiddens, W_out, b_out);
    k_pre<<<dim3(16, 64), 256>>>(hiddens, W_ih0, b_ih0, b_hh0);
    k_zero<<<1, 32>>>();
    k_loop<<<G_, 512, SMEM_LOOP>>>(W_out, b_out);
    k_final<<<1024, 256>>>(mask, out);
}

// round 7
// speedup vs baseline: 4.2865x; 1.1704x over previous
#include <cuda_runtime.h>
#include <cuda_bf16.h>
#include <cstdint>
#include <cstddef>

// ---------------------------------------------------------------------------
// TaggingFNNDecoder: 2-layer LSTM tag decoder. B=32, T=256, D=1024, H=512, K=128
// Round 6: split arrive/wait grid barriers with compute hidden in both barrier
// windows (cell1 h2-half under bar1, next-step cell0 h-part under bar2),
// 512-thread parallel gate reductions, fast NaN-free tanh/sigmoid.
// ---------------------------------------------------------------------------

#define B_  32
#define T_  256
#define D_  1024
#define H_  512
#define K_  128
#define R_  2048    // 4*H gate rows
#define KC0 640     // cell0 reduced k-dim: h1(512) + e(128)
#define KC1 1024    // cell1 k-dim: h1(512) + h2(512)
#define G_  128     // persistent grid size (<= 148 SMs, 1 CTA/SM)

// ------------------------- device scratch ----------------------------------
__device__ float d_pre0[(size_t)T_ * R_ * B_];   // 64 MB [t][row][b]
__device__ float d_W0[(size_t)R_ * KC0];         // [row][ W_hh0 | W_ih0[:,1024:] ]
__device__ float d_W1[(size_t)R_ * KC1];         // [row][ W_ih1 | W_hh1 ]
__device__ float d_bias1[R_];
__device__ float d_h1[2 * H_ * B_];              // double buffered [j][b]
__device__ float d_h2[2 * H_ * B_];
__device__ float d_c1[H_ * B_];
__device__ float d_c2[H_ * B_];
__device__ float d_logit0[K_ * B_];              // [k][b] initial tag logits
__device__ float d_logits[(size_t)T_ * K_ * B_]; // [t][k][b] raw logits

// central barrier counter (monotonic within one launch; reset by k_zero)
__device__ unsigned g_count;

// fast NaN-free activations (errors ~1e-7, well under 1e-3 tolerance)
__device__ __forceinline__ float sigf(float x) {
    return __fdividef(1.0f, 1.0f + __expf(-x));
}
__device__ __forceinline__ float tanhfast(float x) {
    return 1.0f - __fdividef(2.0f, 1.0f + __expf(2.0f * x));
}

// packed fp32x2 helpers
__device__ __forceinline__ unsigned long long pk2(float x) {
    unsigned long long r; unsigned u = __float_as_uint(x);
    asm("mov.b64 %0, {%1, %1};" : "=l"(r) : "r"(u));
    return r;
}
__device__ __forceinline__ void fma2(unsigned long long& a,
                                     unsigned long long x, unsigned long long w) {
    asm("fma.rn.f32x2 %0, %1, %2, %0;" : "+l"(a) : "l"(x), "l"(w));
}
__device__ __forceinline__ void unpk2(float& lo, float& hi, unsigned long long v) {
    unsigned l, h;
    asm("mov.b64 {%0, %1}, %2;" : "=r"(l), "=r"(h) : "l"(v));
    lo = __uint_as_float(l); hi = __uint_as_float(h);
}

// split grid barrier: arrive = syncthreads + red.release.gpu (cumulativity
// publishes the block's prior global stores/atomics); wait = acquire-spin.
__device__ __forceinline__ void gbar_arrive() {
    __syncthreads();
    if (threadIdx.x == 0) {
        asm volatile("red.release.gpu.add.u32 [%0], %1;"
                     :: "l"(&g_count), "r"(1u) : "memory");
    }
}
__device__ __forceinline__ void gbar_wait(unsigned target) {
    if (threadIdx.x == 0) {
        unsigned v;
        do {
            asm volatile("ld.acquire.gpu.u32 %0, [%1];"
                         : "=r"(v) : "l"(&g_count) : "memory");
        } while ((int)(v - target) < 0);
    }
    __syncthreads();
}

// -------------------- setup: pack weights + init states ---------------------
__global__ void k_setup(const float* __restrict__ Wih0, const float* __restrict__ Whh0,
                        const float* __restrict__ Wih1, const float* __restrict__ Whh1,
                        const float* __restrict__ bih1, const float* __restrict__ bhh1,
                        const float* __restrict__ h_t,  const float* __restrict__ c_t,
                        const float* __restrict__ hid,  const float* __restrict__ W_out,
                        const float* __restrict__ b_out) {
    int row = blockIdx.x;          // 0..2047
    int tid = threadIdx.x;         // 256 threads
    // ---- weight pack ----
    const float4* s1 = (const float4*)(Whh0 + (size_t)row * H_);
    float4* dW0 = (float4*)(d_W0 + (size_t)row * KC0);
    for (int i = tid; i < H_ / 4; i += 256) dW0[i] = s1[i];
    const float4* s2 = (const float4*)(Wih0 + (size_t)row * (D_ + K_) + D_);
    for (int i = tid; i < K_ / 4; i += 256) dW0[H_ / 4 + i] = s2[i];
    float4* dW1 = (float4*)(d_W1 + (size_t)row * KC1);
    const float4* s3 = (const float4*)(Wih1 + (size_t)row * H_);
    const float4* s4 = (const float4*)(Whh1 + (size_t)row * H_);
    for (int i = tid; i < H_ / 4; i += 256) { dW1[i] = s3[i]; dW1[H_ / 4 + i] = s4[i]; }
    if (tid == 0) d_bias1[row] = bih1[row] + bhh1[row];

    // ---- logits prefill with output bias (blocks 0..255 <-> t) ----
    if (row < 256) {
        float* dst = d_logits + (size_t)row * K_ * B_;
        for (int i = tid; i < K_ * B_; i += 256) dst[i] = b_out[i >> 5];
    }
    // ---- state transpose (blocks 0..63) ----
    if (row < 64) {
        int idx = row * 256 + tid;                 // 0..16383 = j*32+b
        int j = idx >> 5, b = idx & 31;
        d_h1[idx] = h_t[b * H_ + j];
        d_h2[idx] = h_t[B_ * H_ + b * H_ + j];
        d_c1[idx] = c_t[b * H_ + j];
        d_c2[idx] = c_t[B_ * H_ + b * H_ + j];
    }
    // ---- initial tag logits (blocks 64..95, threads 0..127) ----
    if (row >= 64 && row < 96 && tid < 128) {
        int b = row - 64;                          // batch
        int k = tid;                               // tag
        const float* x  = hid + (size_t)b * T_ * D_;
        const float* wr = W_out + (size_t)k * H_;
        float a0 = 0.f, a1 = 0.f, a2 = 0.f, a3 = 0.f;
        for (int j = 0; j < H_; j += 4) {
            float4 w4 = *(const float4*)(wr + j);
            a0 += w4.x * x[j + 0];
            a1 += w4.y * x[j + 1];
            a2 += w4.z * x[j + 2];
            a3 += w4.w * x[j + 3];
        }
        d_logit0[k * B_ + b] = (a0 + a1) + (a2 + a3) + b_out[k];
    }
}

// reset barrier counter
__global__ void k_zero() {
    if (threadIdx.x == 0) g_count = 0;
}

// -------------- pre-projection SGEMM (FFMA2, K-tile 16) ----------------------
__global__ void __launch_bounds__(256) k_pre(const float* __restrict__ A,
                                             const float* __restrict__ W,
                                             const float* __restrict__ bih,
                                             const float* __restrict__ bhh) {
    __shared__ float As[16][132];
    __shared__ float Bs[16][132];
    int tid = threadIdx.x;
    int m0 = blockIdx.y * 128;
    int n0 = blockIdx.x * 128;
    int lr = tid >> 1;
    int lc = (tid & 1) * 4;
    int ty = tid >> 4;
    int tx = tid & 15;

    unsigned long long acc2[8][4];
#pragma unroll
    for (int i = 0; i < 8; i++)
#pragma unroll
        for (int j = 0; j < 4; j++) acc2[i][j] = 0ull;

    for (int kt = 0; kt < D_; kt += 16) {
        float4 a0 = *(const float4*)&A[(size_t)(m0 + lr) * D_ + kt + lc];
        float4 a1 = *(const float4*)&A[(size_t)(m0 + lr) * D_ + kt + 8 + lc];
        float4 b0 = *(const float4*)&W[(size_t)(n0 + lr) * (D_ + K_) + kt + lc];
        float4 b1 = *(const float4*)&W[(size_t)(n0 + lr) * (D_ + K_) + kt + 8 + lc];
        As[lc + 0][lr] = a0.x; As[lc + 1][lr] = a0.y;
        As[lc + 2][lr] = a0.z; As[lc + 3][lr] = a0.w;
        As[8 + lc + 0][lr] = a1.x; As[8 + lc + 1][lr] = a1.y;
        As[8 + lc + 2][lr] = a1.z; As[8 + lc + 3][lr] = a1.w;
        Bs[lc + 0][lr] = b0.x; Bs[lc + 1][lr] = b0.y;
        Bs[lc + 2][lr] = b0.z; Bs[lc + 3][lr] = b0.w;
        Bs[8 + lc + 0][lr] = b1.x; Bs[8 + lc + 1][lr] = b1.y;
        Bs[8 + lc + 2][lr] = b1.z; Bs[8 + lc + 3][lr] = b1.w;
        __syncthreads();
#pragma unroll 16
        for (int k = 0; k < 16; k++) {
            float4 raA = *(const float4*)&As[k][ty * 4];
            float4 raB = *(const float4*)&As[k][64 + ty * 4];
            ulonglong2 rbA = *(const ulonglong2*)&Bs[k][tx * 4];
            ulonglong2 rbB = *(const ulonglong2*)&Bs[k][64 + tx * 4];
            float ra[8] = {raA.x, raA.y, raA.z, raA.w, raB.x, raB.y, raB.z, raB.w};
#pragma unroll
            for (int i = 0; i < 8; i++) {
                unsigned long long ax = pk2(ra[i]);
                fma2(acc2[i][0], ax, rbA.x);
                fma2(acc2[i][1], ax, rbA.y);
                fma2(acc2[i][2], ax, rbB.x);
                fma2(acc2[i][3], ax, rbB.y);
            }
        }
        __syncthreads();
    }

#pragma unroll
    for (int i = 0; i < 8; i++) {
        int m = m0 + ((i < 4) ? (ty * 4 + i) : (64 + ty * 4 + i - 4));
        int tt = m & 255;
        int bb = m >> 8;
#pragma unroll
        for (int j2 = 0; j2 < 4; j2++) {
            float lo, hi;
            unpk2(lo, hi, acc2[i][j2]);
            int nb = (j2 < 2) ? (n0 + tx * 4 + j2 * 2)
                              : (n0 + 64 + tx * 4 + (j2 - 2) * 2);
            d_pre0[((size_t)tt * R_ + nb + 0) * B_ + bb] = lo + bih[nb] + bhh[nb];
            d_pre0[((size_t)tt * R_ + nb + 1) * B_ + bb] = hi + bih[nb + 1] + bhh[nb + 1];
        }
    }
}

// ------------------------- persistent recurrence -----------------------------
// 128 CTAs x 512 threads (16 warps). CTA c owns units u = c*4..c*4+3 (16 gate
// rows / layer, local row r = g*4+ul) and tag rows via scatter.
// Per step:
//  A: e-dot + gate0 -> h1[t]; arrive bar1; [cell1 h2-half dot]; wait bar1
//  B: cell1 h1-half dot + gate1 -> h2[t]; scatter logits[t]; arrive bar2;
//     [cell0 h-part dot for t+1]; wait bar2
__global__ void __launch_bounds__(512, 1) k_loop(const float* __restrict__ W_out,
                                                 const float* __restrict__ b_out) {
    extern __shared__ float smem[];
    float* w0s     = smem;                    // 640*16  = 10240
    float* w1s     = w0s + KC0 * 16;          // 1024*16 = 16384
    float* woutT   = w1s + KC1 * 16;          // [ul][k] 4*128 = 512
    float* bias1s  = woutT + 512;             // 16 (padded to 32)
    float* parthA  = bias1s + 32;             // 16*16*32 = 8192 (cell0 h partials)
    float* partB   = parthA + 8192;           // 8192 (e partials / cell1 partials)
    float* zps     = partB + 8192;            // 16*32 = 512
    float* rowH    = zps + 512;               // 16*32 = 512
    float* rowE    = rowH + 512;              // 16*32 = 512
    float* zs      = rowE + 512;              // 32
    float* h2s     = zs + 32;                 // 4*32 = 128

    const int c    = blockIdx.x;
    const int tid  = threadIdx.x;
    const int lane = tid & 31;
    const int w    = tid >> 5;                // 16 warps
    const int r_   = tid >> 5;                // row index for 512-thread reduce

    // ---- stage weights into SMEM (once) ----
#pragma unroll
    for (int r = 0; r < 16; r++) {
        int grow = (r >> 2) * H_ + c * 4 + (r & 3);
        const float* src0 = d_W0 + (size_t)grow * KC0;
        for (int k = tid; k < KC0; k += 512) w0s[k * 16 + r] = src0[k];
        const float* src1 = d_W1 + (size_t)grow * KC1;
        for (int k = tid; k < KC1; k += 512) w1s[k * 16 + r] = src1[k];
        if (tid == 0) bias1s[r] = d_bias1[grow];
    }
    {   // W_out columns for this CTA's 4 units: woutT[ul*128 + k]
        int ul2 = tid >> 7, k2 = tid & 127;
        woutT[tid] = W_out[(size_t)k2 * H_ + c * 4 + ul2];
    }
    __syncthreads();

    // ---- per-thread cell state (tid<128): b = tid&31, ul = tid>>5 ----
    float c1_reg = 0.f, c2_reg = 0.f;
    int b = tid & 31, ul = tid >> 5;
    int u = c * 4 + (ul & 3);
    float pre[4];
    if (tid < 128) {
        c1_reg = d_c1[u * 32 + b];
        c2_reg = d_c2[u * 32 + b];
#pragma unroll
        for (int g = 0; g < 4; g++)
            pre[g] = __ldcg(&d_pre0[((size_t)0 * R_ + g * H_ + u) * B_ + b]);
    }

    // ---- prologue: cell0 h-part partials for t=0 (h1 buffer 0) ----
    {
        const float* __restrict__ h1p = d_h1;      // buffer 0
        unsigned long long acc[8];
#pragma unroll
        for (int p = 0; p < 8; p++) acc[p] = 0ull;
        int kb = w * 32;
#pragma unroll 16
        for (int kk = 0; kk < 32; kk++) {
            int k = kb + kk;
            unsigned long long xx = pk2(__ldcg(h1p + k * 32 + lane));
            const ulonglong2* q = (const ulonglong2*)(w0s + k * 16);
            ulonglong2 q0 = q[0], q1 = q[1], q2 = q[2], q3 = q[3];
            fma2(acc[0], xx, q0.x); fma2(acc[1], xx, q0.y);
            fma2(acc[2], xx, q1.x); fma2(acc[3], xx, q1.y);
            fma2(acc[4], xx, q2.x); fma2(acc[5], xx, q2.y);
            fma2(acc[6], xx, q3.x); fma2(acc[7], xx, q3.y);
        }
#pragma unroll
        for (int p = 0; p < 8; p++) {
            float lo, hi; unpk2(lo, hi, acc[p]);
            parthA[(w * 16 + 2 * p + 0) * 32 + lane] = lo;
            parthA[(w * 16 + 2 * p + 1) * 32 + lane] = hi;
        }
    }
    __syncthreads();

    unsigned tgt = G_;

    for (int t = 0; t < T_; t++) {
        const int old = t & 1, nw = old ^ 1;
        float*       __restrict__ h1new = d_h1 + nw  * (H_ * B_);
        const float* __restrict__ h2old = d_h2 + old * (H_ * B_);
        float*       __restrict__ h2new = d_h2 + nw  * (H_ * B_);

        // ======================= phase A: e-dot + gate0 ======================
        {
            unsigned long long acce[8];
#pragma unroll
            for (int p = 0; p < 8; p++) acce[p] = 0ull;
            const float* lg = (t == 0) ? d_logit0
                                       : d_logits + (size_t)(t - 1) * K_ * B_;
            float zp = 0.f;
            int ke0 = w * 8;
#pragma unroll
            for (int kk = 0; kk < 8; kk++) {
                float ev = __expf(__ldcg(lg + (ke0 + kk) * 32 + lane));
                zp += ev;
                unsigned long long xx = pk2(ev);
                const ulonglong2* q = (const ulonglong2*)(w0s + (H_ + ke0 + kk) * 16);
                ulonglong2 q0 = q[0], q1 = q[1], q2 = q[2], q3 = q[3];
                fma2(acce[0], xx, q0.x); fma2(acce[1], xx, q0.y);
                fma2(acce[2], xx, q1.x); fma2(acce[3], xx, q1.y);
                fma2(acce[4], xx, q2.x); fma2(acce[5], xx, q2.y);
                fma2(acce[6], xx, q3.x); fma2(acce[7], xx, q3.y);
            }
            zps[w * 32 + lane] = zp;
#pragma unroll
            for (int p = 0; p < 8; p++) {
                float lo, hi; unpk2(lo, hi, acce[p]);
                partB[(w * 16 + 2 * p + 0) * 32 + lane] = lo;
                partB[(w * 16 + 2 * p + 1) * 32 + lane] = hi;
            }
        }
        __syncthreads();

        // 512-thread parallel row reduction
        {
            float se = 0.f, sh = 0.f;
#pragma unroll
            for (int w2 = 0; w2 < 16; w2++) {
                se += partB[(w2 * 16 + r_) * 32 + lane];
                sh += parthA[(w2 * 16 + r_) * 32 + lane];
            }
            rowE[r_ * 32 + lane] = se;
            rowH[r_ * 32 + lane] = sh;
            if (tid < 32) {
                float z = 0.f;
#pragma unroll
                for (int w2 = 0; w2 < 16; w2++) z += zps[w2 * 32 + tid];
                zs[tid] = z;
            }
        }
        __syncthreads();

        if (tid < 128) {
            float invZ = __fdividef(1.0f, zs[b]);
            float gate[4];
#pragma unroll
            for (int g = 0; g < 4; g++) {
                int r = g * 4 + ul;
                gate[g] = pre[g] + rowH[r * 32 + b] + rowE[r * 32 + b] * invZ;
            }
            float iv = sigf(gate[0]);
            float fv = sigf(gate[1]);
            float gv = tanhfast(gate[2]);
            float ov = sigf(gate[3]);
            c1_reg = fv * c1_reg + iv * gv;
            h1new[u * 32 + b] = ov * tanhfast(c1_reg);
        }
        gbar_arrive();                          // bar1 arrive

        // ===== cell1 dot: h2-half (no h1 dependency) overlaps bar1 wait ======
        unsigned long long acc1[8];
#pragma unroll
        for (int p = 0; p < 8; p++) acc1[p] = 0ull;
        {
            int kb = w * 32;
#pragma unroll 16
            for (int kk = 0; kk < 32; kk++) {
                unsigned long long xx = pk2(__ldcg(h2old + (kb + kk) * 32 + lane));
                const ulonglong2* q = (const ulonglong2*)(w1s + (H_ + kb + kk) * 16);
                ulonglong2 q0 = q[0], q1 = q[1], q2 = q[2], q3 = q[3];
                fma2(acc1[0], xx, q0.x); fma2(acc1[1], xx, q0.y);
                fma2(acc1[2], xx, q1.x); fma2(acc1[3], xx, q1.y);
                fma2(acc1[4], xx, q2.x); fma2(acc1[5], xx, q2.y);
                fma2(acc1[6], xx, q3.x); fma2(acc1[7], xx, q3.y);
            }
        }
        gbar_wait(tgt); tgt += G_;              // bar1 wait (h1[t] now global)

        // ======================= phase B: cell1 h1-half ======================
        {
            int kb = w * 32;
#pragma unroll 16
            for (int kk = 0; kk < 32; kk++) {
                unsigned long long xx = pk2(__ldcg(h1new + (kb + kk) * 32 + lane));
                const ulonglong2* q = (const ulonglong2*)(w1s + (kb + kk) * 16);
                ulonglong2 q0 = q[0], q1 = q[1], q2 = q[2], q3 = q[3];
                fma2(acc1[0], xx, q0.x); fma2(acc1[1], xx, q0.y);
                fma2(acc1[2], xx, q1.x); fma2(acc1[3], xx, q1.y);
                fma2(acc1[4], xx, q2.x); fma2(acc1[5], xx, q2.y);
                fma2(acc1[6], xx, q3.x); fma2(acc1[7], xx, q3.y);
            }
#pragma unroll
            for (int p = 0; p < 8; p++) {
                float lo, hi; unpk2(lo, hi, acc1[p]);
                partB[(w * 16 + 2 * p + 0) * 32 + lane] = lo;
                partB[(w * 16 + 2 * p + 1) * 32 + lane] = hi;
            }
        }
        __syncthreads();

        {   // 512-thread row reduction
            float s = 0.f;
#pragma unroll
            for (int w2 = 0; w2 < 16; w2++) s += partB[(w2 * 16 + r_) * 32 + lane];
            rowH[r_ * 32 + lane] = s;
        }
        __syncthreads();

        if (tid < 128) {
            float gate[4];
#pragma unroll
            for (int g = 0; g < 4; g++) {
                int r = g * 4 + ul;
                gate[g] = bias1s[r] + rowH[r * 32 + b];
            }
            float iv = sigf(gate[0]);
            float fv = sigf(gate[1]);
            float gv = tanhfast(gate[2]);
            float ov = sigf(gate[3]);
            c2_reg = fv * c2_reg + iv * gv;
            float h2v = ov * tanhfast(c2_reg);
            h2new[u * 32 + b] = h2v;
            h2s[(ul & 3) * 32 + b] = h2v;
        }
        __syncthreads();

        // scatter: warp w owns tags k = w*8..w*8+7; lane = batch
        {
            float h0 = h2s[lane];
            float h1v = h2s[32 + lane];
            float h2q = h2s[64 + lane];
            float h3 = h2s[96 + lane];
            float* dstl = d_logits + ((size_t)t * K_) * B_;
            int k0 = w * 8;
#pragma unroll
            for (int kk = 0; kk < 8; kk++) {
                int kq = k0 + kk;
                float v = woutT[kq] * h0 + woutT[128 + kq] * h1v
                        + woutT[256 + kq] * h2q + woutT[384 + kq] * h3;
                atomicAdd(dstl + kq * B_ + lane, v);
            }
        }
        // prefetch pre0 for next step
        if (tid < 128) {
            int tn = (t + 1 < T_) ? (t + 1) : t;
#pragma unroll
            for (int g = 0; g < 4; g++)
                pre[g] = __ldcg(&d_pre0[((size_t)tn * R_ + g * H_ + u) * B_ + b]);
        }
        gbar_arrive();                          // bar2 arrive

        // ==== cell0 h-part dot for step t+1 (uses h1[t]) overlaps bar2 =======
        {
            unsigned long long acc[8];
#pragma unroll
            for (int p = 0; p < 8; p++) acc[p] = 0ull;
            int kb = w * 32;
#pragma unroll 16
            for (int kk = 0; kk < 32; kk++) {
                int k = kb + kk;
                unsigned long long xx = pk2(__ldcg(h1new + k * 32 + lane));
                const ulonglong2* q = (const ulonglong2*)(w0s + k * 16);
                ulonglong2 q0 = q[0], q1 = q[1], q2 = q[2], q3 = q[3];
                fma2(acc[0], xx, q0.x); fma2(acc[1], xx, q0.y);
                fma2(acc[2], xx, q1.x); fma2(acc[3], xx, q1.y);
                fma2(acc[4], xx, q2.x); fma2(acc[5], xx, q2.y);
                fma2(acc[6], xx, q3.x); fma2(acc[7], xx, q3.y);
            }
#pragma unroll
            for (int p = 0; p < 8; p++) {
                float lo, hi; unpk2(lo, hi, acc[p]);
                parthA[(w * 16 + 2 * p + 0) * 32 + lane] = lo;
                parthA[(w * 16 + 2 * p + 1) * 32 + lane] = hi;
            }
        }
        __syncthreads();
        gbar_wait(tgt); tgt += G_;              // bar2 wait (logits[t] global)
    }
}

// --------------------------- final masked softmax ----------------------------
__global__ void __launch_bounds__(256) k_final(const float* __restrict__ mask,
                                               float* __restrict__ out) {
    int tid = threadIdx.x, lane = tid & 31, w = tid >> 5;
    int gidx = blockIdx.x * 8 + w;             // 0..8191
    int b = gidx >> 8, t = gidx & 255;
    float pen = (1.0f - mask[b * T_ + t]) * -1e32f;
    float v[4];
#pragma unroll
    for (int i = 0; i < 4; i++)
        v[i] = d_logits[((size_t)t * K_ + lane + 32 * i) * B_ + b] + pen;
    float mx = fmaxf(fmaxf(v[0], v[1]), fmaxf(v[2], v[3]));
#pragma unroll
    for (int o = 16; o > 0; o >>= 1) mx = fmaxf(mx, __shfl_xor_sync(~0u, mx, o));
    float s = 0.f;
#pragma unroll
    for (int i = 0; i < 4; i++) { v[i] = __expf(v[i] - mx); s += v[i]; }
#pragma unroll
    for (int o = 16; o > 0; o >>= 1) s += __shfl_xor_sync(~0u, s, o);
    float inv = 1.0f / s;
#pragma unroll
    for (int i = 0; i < 4; i++)
        out[((size_t)b * T_ + t) * K_ + lane + 32 * i] = v[i] * inv;
}

// ----------------------------------------------------------------------------
extern "C" void kernel_launch(void* const* d_in, const int* in_sizes, int n_in,
                              void* d_out, int out_size) {
    const float* hiddens = (const float*)d_in[0];
    const float* h_t     = (const float*)d_in[1];
    const float* c_t     = (const float*)d_in[2];
    const float* mask    = (const float*)d_in[3];
    const float* W_out   = (const float*)d_in[4];
    const float* b_out   = (const float*)d_in[5];
    const float* W_ih0   = (const float*)d_in[6];
    const float* W_hh0   = (const float*)d_in[7];
    const float* b_ih0   = (const float*)d_in[8];
    const float* b_hh0   = (const float*)d_in[9];
    const float* W_ih1   = (const float*)d_in[10];
    const float* W_hh1   = (const float*)d_in[11];
    const float* b_ih1   = (const float*)d_in[12];
    const float* b_hh1   = (const float*)d_in[13];
    float* out = (float*)d_out;

    // SMEM floats: w0s 10240 + w1s 16384 + woutT 512 + bias1s 32 + parthA 8192
    //            + partB 8192 + zps 512 + rowH 512 + rowE 512 + zs 32 + h2s 128
    //            = 45248 floats = 180992 bytes
    const int SMEM_LOOP = 45248 * 4;
    cudaFuncSetAttribute(k_loop, cudaFuncAttributeMaxDynamicSharedMemorySize, SMEM_LOOP);

    // launch order: slot 3 (the one ncu captures) = k_loop
    k_setup<<<R_, 256>>>(W_ih0, W_hh0, W_ih1, W_hh1, b_ih1, b_hh1,
                         h_t, c_t, hiddens, W_out, b_out);
    k_pre<<<dim3(16, 64), 256>>>(hiddens, W_ih0, b_ih0, b_hh0);
    k_zero<<<1, 32>>>();
    k_loop<<<G_, 512, SMEM_LOOP>>>(W_out, b_out);
    k_final<<<1024, 256>>>(mask, out);
}

// round 8
// speedup vs baseline: 4.6217x; 1.0782x over previous
#include <cuda_runtime.h>
#include <cuda_bf16.h>
#include <cstdint>
#include <cstddef>

// ---------------------------------------------------------------------------
// TaggingFNNDecoder: 2-layer LSTM tag decoder. B=32, T=256, D=1024, H=512, K=128
// Round 7: hybrid lane mapping (4 rows x 4 batches per lane) in the big dot
// loops -> coalesced weight LDS (1 wavefront/k instead of 4). Stride-33
// partial arrays. Everything else (split barriers, overlap, FFMA2) kept.
// ---------------------------------------------------------------------------

#define B_  32
#define T_  256
#define D_  1024
#define H_  512
#define K_  128
#define R_  2048    // 4*H gate rows
#define KC0 640     // cell0 reduced k-dim: h1(512) + e(128)
#define KC1 1024    // cell1 k-dim: h1(512) + h2(512)
#define G_  128     // persistent grid size (<= 148 SMs, 1 CTA/SM)
#define PS  33      // padded row stride for partial arrays

// ------------------------- device scratch ----------------------------------
__device__ float d_pre0[(size_t)T_ * R_ * B_];   // 64 MB [t][row][b]
__device__ float d_W0[(size_t)R_ * KC0];         // [row][ W_hh0 | W_ih0[:,1024:] ]
__device__ float d_W1[(size_t)R_ * KC1];         // [row][ W_ih1 | W_hh1 ]
__device__ float d_bias1[R_];
__device__ float d_h1[2 * H_ * B_];              // double buffered [j][b]
__device__ float d_h2[2 * H_ * B_];
__device__ float d_c1[H_ * B_];
__device__ float d_c2[H_ * B_];
__device__ float d_logit0[K_ * B_];              // [k][b] initial tag logits
__device__ float d_logits[(size_t)T_ * K_ * B_]; // [t][k][b] raw logits

// central barrier counter (monotonic within one launch; reset by k_zero)
__device__ unsigned g_count;

// fast NaN-free activations (errors ~1e-7, well under 1e-3 tolerance)
__device__ __forceinline__ float sigf(float x) {
    return __fdividef(1.0f, 1.0f + __expf(-x));
}
__device__ __forceinline__ float tanhfast(float x) {
    return 1.0f - __fdividef(2.0f, 1.0f + __expf(2.0f * x));
}

// packed fp32x2 helpers
__device__ __forceinline__ unsigned long long pk2(float x) {
    unsigned long long r; unsigned u = __float_as_uint(x);
    asm("mov.b64 %0, {%1, %1};" : "=l"(r) : "r"(u));
    return r;
}
__device__ __forceinline__ unsigned long long pk(float a, float b) {
    unsigned long long r;
    asm("mov.b64 %0, {%1, %2};" : "=l"(r) : "f"(a), "f"(b));
    return r;
}
__device__ __forceinline__ void fma2(unsigned long long& a,
                                     unsigned long long x, unsigned long long w) {
    asm("fma.rn.f32x2 %0, %1, %2, %0;" : "+l"(a) : "l"(x), "l"(w));
}
__device__ __forceinline__ void unpk2(float& lo, float& hi, unsigned long long v) {
    unsigned l, h;
    asm("mov.b64 {%0, %1}, %2;" : "=r"(l), "=r"(h) : "l"(v));
    lo = __uint_as_float(l); hi = __uint_as_float(h);
}
__device__ __forceinline__ float4 ldcg4(const float* p) {
    float4 v;
    asm("ld.global.cg.v4.f32 {%0,%1,%2,%3}, [%4];"
        : "=f"(v.x), "=f"(v.y), "=f"(v.z), "=f"(v.w) : "l"(p));
    return v;
}

// split grid barrier: arrive = syncthreads + red.release.gpu; wait = acquire-spin
__device__ __forceinline__ void gbar_arrive() {
    __syncthreads();
    if (threadIdx.x == 0) {
        asm volatile("red.release.gpu.add.u32 [%0], %1;"
                     :: "l"(&g_count), "r"(1u) : "memory");
    }
}
__device__ __forceinline__ void gbar_wait(unsigned target) {
    if (threadIdx.x == 0) {
        unsigned v;
        do {
            asm volatile("ld.acquire.gpu.u32 %0, [%1];"
                         : "=r"(v) : "l"(&g_count) : "memory");
        } while ((int)(v - target) < 0);
    }
    __syncthreads();
}

// hybrid dot body: warp covers k-slice [x 32 values]; lane = (r4, b8) computes
// rows r4..r4+3 of the 16 CTA rows x batches b4..b4+3. acc[rr][bp] packs
// batch pairs. wbase: k-major weights (16 floats per k), xsrc: [k][b] global.
__device__ __forceinline__ void dot32(unsigned long long acc[4][2],
                                      const float* __restrict__ wbase,
                                      const float* __restrict__ xsrc,
                                      int r4, int b4) {
#pragma unroll 8
    for (int kk = 0; kk < 32; kk++) {
        float4 wv = *(const float4*)(wbase + kk * 16 + r4);
        float4 xv = ldcg4(xsrc + kk * 32 + b4);
        unsigned long long x01 = pk(xv.x, xv.y);
        unsigned long long x23 = pk(xv.z, xv.w);
        unsigned long long w0p = pk2(wv.x), w1p = pk2(wv.y);
        unsigned long long w2p = pk2(wv.z), w3p = pk2(wv.w);
        fma2(acc[0][0], x01, w0p); fma2(acc[0][1], x23, w0p);
        fma2(acc[1][0], x01, w1p); fma2(acc[1][1], x23, w1p);
        fma2(acc[2][0], x01, w2p); fma2(acc[2][1], x23, w2p);
        fma2(acc[3][0], x01, w3p); fma2(acc[3][1], x23, w3p);
    }
}

__device__ __forceinline__ void store_acc(float* part, int wbase_row,
                                          unsigned long long acc[4][2],
                                          int r4, int b4) {
#pragma unroll
    for (int rr = 0; rr < 4; rr++) {
#pragma unroll
        for (int bp = 0; bp < 2; bp++) {
            float lo, hi;
            unpk2(lo, hi, acc[rr][bp]);
            float* p = part + (wbase_row + r4 + rr) * PS + b4 + 2 * bp;
            p[0] = lo; p[1] = hi;
        }
    }
}

// -------------------- setup: pack weights + init states ---------------------
__global__ void k_setup(const float* __restrict__ Wih0, const float* __restrict__ Whh0,
                        const float* __restrict__ Wih1, const float* __restrict__ Whh1,
                        const float* __restrict__ bih1, const float* __restrict__ bhh1,
                        const float* __restrict__ h_t,  const float* __restrict__ c_t,
                        const float* __restrict__ hid,  const float* __restrict__ W_out,
                        const float* __restrict__ b_out) {
    int row = blockIdx.x;          // 0..2047
    int tid = threadIdx.x;         // 256 threads
    // ---- weight pack ----
    const float4* s1 = (const float4*)(Whh0 + (size_t)row * H_);
    float4* dW0 = (float4*)(d_W0 + (size_t)row * KC0);
    for (int i = tid; i < H_ / 4; i += 256) dW0[i] = s1[i];
    const float4* s2 = (const float4*)(Wih0 + (size_t)row * (D_ + K_) + D_);
    for (int i = tid; i < K_ / 4; i += 256) dW0[H_ / 4 + i] = s2[i];
    float4* dW1 = (float4*)(d_W1 + (size_t)row * KC1);
    const float4* s3 = (const float4*)(Wih1 + (size_t)row * H_);
    const float4* s4 = (const float4*)(Whh1 + (size_t)row * H_);
    for (int i = tid; i < H_ / 4; i += 256) { dW1[i] = s3[i]; dW1[H_ / 4 + i] = s4[i]; }
    if (tid == 0) d_bias1[row] = bih1[row] + bhh1[row];

    // ---- logits prefill with output bias (blocks 0..255 <-> t) ----
    if (row < 256) {
        float* dst = d_logits + (size_t)row * K_ * B_;
        for (int i = tid; i < K_ * B_; i += 256) dst[i] = b_out[i >> 5];
    }
    // ---- state transpose (blocks 0..63) ----
    if (row < 64) {
        int idx = row * 256 + tid;                 // 0..16383 = j*32+b
        int j = idx >> 5, b = idx & 31;
        d_h1[idx] = h_t[b * H_ + j];
        d_h2[idx] = h_t[B_ * H_ + b * H_ + j];
        d_c1[idx] = c_t[b * H_ + j];
        d_c2[idx] = c_t[B_ * H_ + b * H_ + j];
    }
    // ---- initial tag logits (blocks 64..95, threads 0..127) ----
    if (row >= 64 && row < 96 && tid < 128) {
        int b = row - 64;                          // batch
        int k = tid;                               // tag
        const float* x  = hid + (size_t)b * T_ * D_;
        const float* wr = W_out + (size_t)k * H_;
        float a0 = 0.f, a1 = 0.f, a2 = 0.f, a3 = 0.f;
        for (int j = 0; j < H_; j += 4) {
            float4 w4 = *(const float4*)(wr + j);
            a0 += w4.x * x[j + 0];
            a1 += w4.y * x[j + 1];
            a2 += w4.z * x[j + 2];
            a3 += w4.w * x[j + 3];
        }
        d_logit0[k * B_ + b] = (a0 + a1) + (a2 + a3) + b_out[k];
    }
}

// reset barrier counter
__global__ void k_zero() {
    if (threadIdx.x == 0) g_count = 0;
}

// -------------- pre-projection SGEMM (FFMA2, K-tile 16) ----------------------
__global__ void __launch_bounds__(256) k_pre(const float* __restrict__ A,
                                             const float* __restrict__ W,
                                             const float* __restrict__ bih,
                                             const float* __restrict__ bhh) {
    __shared__ float As[16][132];
    __shared__ float Bs[16][132];
    int tid = threadIdx.x;
    int m0 = blockIdx.y * 128;
    int n0 = blockIdx.x * 128;
    int lr = tid >> 1;
    int lc = (tid & 1) * 4;
    int ty = tid >> 4;
    int tx = tid & 15;

    unsigned long long acc2[8][4];
#pragma unroll
    for (int i = 0; i < 8; i++)
#pragma unroll
        for (int j = 0; j < 4; j++) acc2[i][j] = 0ull;

    for (int kt = 0; kt < D_; kt += 16) {
        float4 a0 = *(const float4*)&A[(size_t)(m0 + lr) * D_ + kt + lc];
        float4 a1 = *(const float4*)&A[(size_t)(m0 + lr) * D_ + kt + 8 + lc];
        float4 b0 = *(const float4*)&W[(size_t)(n0 + lr) * (D_ + K_) + kt + lc];
        float4 b1 = *(const float4*)&W[(size_t)(n0 + lr) * (D_ + K_) + kt + 8 + lc];
        As[lc + 0][lr] = a0.x; As[lc + 1][lr] = a0.y;
        As[lc + 2][lr] = a0.z; As[lc + 3][lr] = a0.w;
        As[8 + lc + 0][lr] = a1.x; As[8 + lc + 1][lr] = a1.y;
        As[8 + lc + 2][lr] = a1.z; As[8 + lc + 3][lr] = a1.w;
        Bs[lc + 0][lr] = b0.x; Bs[lc + 1][lr] = b0.y;
        Bs[lc + 2][lr] = b0.z; Bs[lc + 3][lr] = b0.w;
        Bs[8 + lc + 0][lr] = b1.x; Bs[8 + lc + 1][lr] = b1.y;
        Bs[8 + lc + 2][lr] = b1.z; Bs[8 + lc + 3][lr] = b1.w;
        __syncthreads();
#pragma unroll 16
        for (int k = 0; k < 16; k++) {
            float4 raA = *(const float4*)&As[k][ty * 4];
            float4 raB = *(const float4*)&As[k][64 + ty * 4];
            ulonglong2 rbA = *(const ulonglong2*)&Bs[k][tx * 4];
            ulonglong2 rbB = *(const ulonglong2*)&Bs[k][64 + tx * 4];
            float ra[8] = {raA.x, raA.y, raA.z, raA.w, raB.x, raB.y, raB.z, raB.w};
#pragma unroll
            for (int i = 0; i < 8; i++) {
                unsigned long long ax = pk2(ra[i]);
                fma2(acc2[i][0], ax, rbA.x);
                fma2(acc2[i][1], ax, rbA.y);
                fma2(acc2[i][2], ax, rbB.x);
                fma2(acc2[i][3], ax, rbB.y);
            }
        }
        __syncthreads();
    }

#pragma unroll
    for (int i = 0; i < 8; i++) {
        int m = m0 + ((i < 4) ? (ty * 4 + i) : (64 + ty * 4 + i - 4));
        int tt = m & 255;
        int bb = m >> 8;
#pragma unroll
        for (int j2 = 0; j2 < 4; j2++) {
            float lo, hi;
            unpk2(lo, hi, acc2[i][j2]);
            int nb = (j2 < 2) ? (n0 + tx * 4 + j2 * 2)
                              : (n0 + 64 + tx * 4 + (j2 - 2) * 2);
            d_pre0[((size_t)tt * R_ + nb + 0) * B_ + bb] = lo + bih[nb] + bhh[nb];
            d_pre0[((size_t)tt * R_ + nb + 1) * B_ + bb] = hi + bih[nb + 1] + bhh[nb + 1];
        }
    }
}

// ------------------------- persistent recurrence -----------------------------
__global__ void __launch_bounds__(512, 1) k_loop(const float* __restrict__ W_out,
                                                 const float* __restrict__ b_out) {
    extern __shared__ float smem[];
    float* w0s     = smem;                    // 640*16  = 10240
    float* w1s     = w0s + KC0 * 16;          // 1024*16 = 16384
    float* woutT   = w1s + KC1 * 16;          // [ul][k] 4*128 = 512
    float* bias1s  = woutT + 512;             // 16 (padded to 32)
    float* parthA  = bias1s + 32;             // 256*PS = 8448 (cell0 h partials)
    float* partB   = parthA + 256 * PS;       // 8448 (e / cell1 partials)
    float* zps     = partB + 256 * PS;        // 16*32 = 512
    float* rowH    = zps + 512;               // 16*PS = 528
    float* rowE    = rowH + 16 * PS;          // 528
    float* zs      = rowE + 16 * PS;          // 32
    float* h2s     = zs + 32;                 // 4*32 = 128

    const int c    = blockIdx.x;
    const int tid  = threadIdx.x;
    const int lane = tid & 31;
    const int w    = tid >> 5;                // 16 warps
    const int r_   = tid >> 5;                // row index for 512-thread reduce
    const int r4   = (lane >> 3) << 2;        // hybrid row-group base
    const int b4   = (lane & 7) << 2;         // hybrid batch base

    // ---- stage weights into SMEM (once) ----
#pragma unroll
    for (int r = 0; r < 16; r++) {
        int grow = (r >> 2) * H_ + c * 4 + (r & 3);
        const float* src0 = d_W0 + (size_t)grow * KC0;
        for (int k = tid; k < KC0; k += 512) w0s[k * 16 + r] = src0[k];
        const float* src1 = d_W1 + (size_t)grow * KC1;
        for (int k = tid; k < KC1; k += 512) w1s[k * 16 + r] = src1[k];
        if (tid == 0) bias1s[r] = d_bias1[grow];
    }
    {   // W_out columns for this CTA's 4 units: woutT[ul*128 + k]
        int ul2 = tid >> 7, k2 = tid & 127;
        woutT[tid] = W_out[(size_t)k2 * H_ + c * 4 + ul2];
    }
    __syncthreads();

    // ---- per-thread cell state (tid<128): b = tid&31, ul = tid>>5 ----
    float c1_reg = 0.f, c2_reg = 0.f;
    int b = tid & 31, ul = tid >> 5;
    int u = c * 4 + (ul & 3);
    float pre[4];
    if (tid < 128) {
        c1_reg = d_c1[u * 32 + b];
        c2_reg = d_c2[u * 32 + b];
#pragma unroll
        for (int g = 0; g < 4; g++)
            pre[g] = __ldcg(&d_pre0[((size_t)0 * R_ + g * H_ + u) * B_ + b]);
    }

    // ---- prologue: cell0 h-part partials for t=0 (h1 buffer 0) ----
    {
        unsigned long long acc[4][2];
#pragma unroll
        for (int i = 0; i < 4; i++) { acc[i][0] = 0ull; acc[i][1] = 0ull; }
        dot32(acc, w0s + (w * 32) * 16, d_h1 + (w * 32) * 32, r4, b4);
        store_acc(parthA, w * 16, acc, r4, b4);
    }
    __syncthreads();

    unsigned tgt = G_;

    for (int t = 0; t < T_; t++) {
        const int old = t & 1, nw = old ^ 1;
        float*       __restrict__ h1new = d_h1 + nw  * (H_ * B_);
        const float* __restrict__ h2old = d_h2 + old * (H_ * B_);
        float*       __restrict__ h2new = d_h2 + nw  * (H_ * B_);

        // ======================= phase A: e-dot + gate0 ======================
        {
            unsigned long long acce[8];
#pragma unroll
            for (int p = 0; p < 8; p++) acce[p] = 0ull;
            const float* lg = (t == 0) ? d_logit0
                                       : d_logits + (size_t)(t - 1) * K_ * B_;
            float zp = 0.f;
            int ke0 = w * 8;
#pragma unroll
            for (int kk = 0; kk < 8; kk++) {
                float ev = __expf(__ldcg(lg + (ke0 + kk) * 32 + lane));
                zp += ev;
                unsigned long long xx = pk2(ev);
                const ulonglong2* q = (const ulonglong2*)(w0s + (H_ + ke0 + kk) * 16);
                ulonglong2 q0 = q[0], q1 = q[1], q2 = q[2], q3 = q[3];
                fma2(acce[0], xx, q0.x); fma2(acce[1], xx, q0.y);
                fma2(acce[2], xx, q1.x); fma2(acce[3], xx, q1.y);
                fma2(acce[4], xx, q2.x); fma2(acce[5], xx, q2.y);
                fma2(acce[6], xx, q3.x); fma2(acce[7], xx, q3.y);
            }
            zps[w * 32 + lane] = zp;
#pragma unroll
            for (int p = 0; p < 8; p++) {
                float lo, hi; unpk2(lo, hi, acce[p]);
                partB[(w * 16 + 2 * p + 0) * PS + lane] = lo;
                partB[(w * 16 + 2 * p + 1) * PS + lane] = hi;
            }
        }
        __syncthreads();

        // 512-thread parallel row reduction
        {
            float se = 0.f, sh = 0.f;
#pragma unroll
            for (int w2 = 0; w2 < 16; w2++) {
                se += partB[(w2 * 16 + r_) * PS + lane];
                sh += parthA[(w2 * 16 + r_) * PS + lane];
            }
            rowE[r_ * PS + lane] = se;
            rowH[r_ * PS + lane] = sh;
            if (tid < 32) {
                float z = 0.f;
#pragma unroll
                for (int w2 = 0; w2 < 16; w2++) z += zps[w2 * 32 + tid];
                zs[tid] = z;
            }
        }
        __syncthreads();

        if (tid < 128) {
            float invZ = __fdividef(1.0f, zs[b]);
            float gate[4];
#pragma unroll
            for (int g = 0; g < 4; g++) {
                int r = g * 4 + ul;
                gate[g] = pre[g] + rowH[r * PS + b] + rowE[r * PS + b] * invZ;
            }
            float iv = sigf(gate[0]);
            float fv = sigf(gate[1]);
            float gv = tanhfast(gate[2]);
            float ov = sigf(gate[3]);
            c1_reg = fv * c1_reg + iv * gv;
            h1new[u * 32 + b] = ov * tanhfast(c1_reg);
        }
        gbar_arrive();                          // bar1 arrive

        // ===== cell1 dot: h2-half (no h1 dependency) overlaps bar1 wait ======
        unsigned long long acc1[4][2];
#pragma unroll
        for (int i = 0; i < 4; i++) { acc1[i][0] = 0ull; acc1[i][1] = 0ull; }
        dot32(acc1, w1s + (H_ + w * 32) * 16, h2old + (w * 32) * 32, r4, b4);
        gbar_wait(tgt); tgt += G_;              // bar1 wait (h1[t] now global)

        // ======================= phase B: cell1 h1-half ======================
        dot32(acc1, w1s + (w * 32) * 16, h1new + (w * 32) * 32, r4, b4);
        store_acc(partB, w * 16, acc1, r4, b4);
        __syncthreads();

        {   // 512-thread row reduction
            float s = 0.f;
#pragma unroll
            for (int w2 = 0; w2 < 16; w2++) s += partB[(w2 * 16 + r_) * PS + lane];
            rowH[r_ * PS + lane] = s;
        }
        __syncthreads();

        if (tid < 128) {
            float gate[4];
#pragma unroll
            for (int g = 0; g < 4; g++) {
                int r = g * 4 + ul;
                gate[g] = bias1s[r] + rowH[r * PS + b];
            }
            float iv = sigf(gate[0]);
            float fv = sigf(gate[1]);
            float gv = tanhfast(gate[2]);
            float ov = sigf(gate[3]);
            c2_reg = fv * c2_reg + iv * gv;
            float h2v = ov * tanhfast(c2_reg);
            h2new[u * 32 + b] = h2v;
            h2s[(ul & 3) * 32 + b] = h2v;
        }
        __syncthreads();

        // scatter: warp w owns tags k = w*8..w*8+7; lane = batch
        {
            float h0 = h2s[lane];
            float h1v = h2s[32 + lane];
            float h2q = h2s[64 + lane];
            float h3 = h2s[96 + lane];
            float* dstl = d_logits + ((size_t)t * K_) * B_;
            int k0 = w * 8;
#pragma unroll
            for (int kk = 0; kk < 8; kk++) {
                int kq = k0 + kk;
                float v = woutT[kq] * h0 + woutT[128 + kq] * h1v
                        + woutT[256 + kq] * h2q + woutT[384 + kq] * h3;
                atomicAdd(dstl + kq * B_ + lane, v);
            }
        }
        // prefetch pre0 for next step
        if (tid < 128) {
            int tn = (t + 1 < T_) ? (t + 1) : t;
#pragma unroll
            for (int g = 0; g < 4; g++)
                pre[g] = __ldcg(&d_pre0[((size_t)tn * R_ + g * H_ + u) * B_ + b]);
        }
        gbar_arrive();                          // bar2 arrive

        // ==== cell0 h-part dot for step t+1 (uses h1[t]) overlaps bar2 =======
        {
            unsigned long long acc[4][2];
#pragma unroll
            for (int i = 0; i < 4; i++) { acc[i][0] = 0ull; acc[i][1] = 0ull; }
            dot32(acc, w0s + (w * 32) * 16, h1new + (w * 32) * 32, r4, b4);
            store_acc(parthA, w * 16, acc, r4, b4);
        }
        __syncthreads();
        gbar_wait(tgt); tgt += G_;              // bar2 wait (logits[t] global)
    }
}

// --------------------------- final masked softmax ----------------------------
__global__ void __launch_bounds__(256) k_final(const float* __restrict__ mask,
                                               float* __restrict__ out) {
    int tid = threadIdx.x, lane = tid & 31, w = tid >> 5;
    int gidx = blockIdx.x * 8 + w;             // 0..8191
    int b = gidx >> 8, t = gidx & 255;
    float pen = (1.0f - mask[b * T_ + t]) * -1e32f;
    float v[4];
#pragma unroll
    for (int i = 0; i < 4; i++)
        v[i] = d_logits[((size_t)t * K_ + lane + 32 * i) * B_ + b] + pen;
    float mx = fmaxf(fmaxf(v[0], v[1]), fmaxf(v[2], v[3]));
#pragma unroll
    for (int o = 16; o > 0; o >>= 1) mx = fmaxf(mx, __shfl_xor_sync(~0u, mx, o));
    float s = 0.f;
#pragma unroll
    for (int i = 0; i < 4; i++) { v[i] = __expf(v[i] - mx); s += v[i]; }
#pragma unroll
    for (int o = 16; o > 0; o >>= 1) s += __shfl_xor_sync(~0u, s, o);
    float inv = 1.0f / s;
#pragma unroll
    for (int i = 0; i < 4; i++)
        out[((size_t)b * T_ + t) * K_ + lane + 32 * i] = v[i] * inv;
}

// ----------------------------------------------------------------------------
extern "C" void kernel_launch(void* const* d_in, const int* in_sizes, int n_in,
                              void* d_out, int out_size) {
    const float* hiddens = (const float*)d_in[0];
    const float* h_t     = (const float*)d_in[1];
    const float* c_t     = (const float*)d_in[2];
    const float* mask    = (const float*)d_in[3];
    const float* W_out   = (const float*)d_in[4];
    const float* b_out   = (const float*)d_in[5];
    const float* W_ih0   = (const float*)d_in[6];
    const float* W_hh0   = (const float*)d_in[7];
    const float* b_ih0   = (const float*)d_in[8];
    const float* b_hh0   = (const float*)d_in[9];
    const float* W_ih1   = (const float*)d_in[10];
    const float* W_hh1   = (const float*)d_in[11];
    const float* b_ih1   = (const float*)d_in[12];
    const float* b_hh1   = (const float*)d_in[13];
    float* out = (float*)d_out;

    // SMEM floats: 10240+16384+512+32 + 8448 + 8448 + 512 + 528 + 528 + 32 + 128
    //            = 45792 floats = 183168 bytes
    const int SMEM_LOOP = 45792 * 4;
    cudaFuncSetAttribute(k_loop, cudaFuncAttributeMaxDynamicSharedMemorySize, SMEM_LOOP);

    // launch order: slot 3 (the one ncu captures) = k_loop
    k_setup<<<R_, 256>>>(W_ih0, W_hh0, W_ih1, W_hh1, b_ih1, b_hh1,
                         h_t, c_t, hiddens, W_out, b_out);
    k_pre<<<dim3(16, 64), 256>>>(hiddens, W_ih0, b_ih0, b_hh0);
    k_zero<<<1, 32>>>();
    k_loop<<<G_, 512, SMEM_LOOP>>>(W_out, b_out);
    k_final<<<1024, 256>>>(mask, out);
}